// round 14
// baseline (speedup 1.0000x reference)
#include <cuda_runtime.h>
#include <cuda_fp16.h>
#include <math.h>
#include <stdint.h>

// ---------------- problem constants ----------------
#define T_DIM   64
#define HW_DIM  729
#define M_TRK   512
#define DM      1152
#define NH      8
#define DH      144
#define MQ      (T_DIM * M_TRK)    // 32768
#define MK      (T_DIM * HW_DIM)   // 46656
#define MQB     (MQ / 128)         // 256
#define MKB     ((MK + 127) / 128) // 365

// ---------------- device scratch ----------------
__device__ __half g_Qg[(size_t)MQ * DM];
__device__ __half g_Kg[(size_t)MK * DM];
__device__ __half g_TTh[(size_t)MQ * DM];
__device__ __half g_Fh[(size_t)MK * DM];
__device__ __half g_Wq[(size_t)DM * DM];
__device__ __half g_Wk[(size_t)DM * DM];
__device__ __half g_Wo[(size_t)DM * DM];
__device__ __half g_Qh[(size_t)MQ * DM];
__device__ __half g_Kh[(size_t)MK * DM];
__device__ __half g_Sh[(size_t)MQ * DM];
__device__ float2 g_rtab[(size_t)HW_DIM * 576];

__device__ __forceinline__ uint32_t smem_u32(const void* p) {
    uint32_t a;
    asm("{ .reg .u64 t; cvta.to.shared.u64 t, %1; cvt.u32.u64 %0, t; }" : "=r"(a) : "l"(p));
    return a;
}
__device__ __forceinline__ void cp16(uint32_t dst, const void* src) {
    asm volatile("cp.async.cg.shared.global [%0], [%1], 16;" :: "r"(dst), "l"(src));
}
__device__ __forceinline__ void ldm4(uint32_t addr, uint32_t* r) {
    asm volatile("ldmatrix.sync.aligned.m8n8.x4.shared.b16 {%0,%1,%2,%3}, [%4];"
                 : "=r"(r[0]), "=r"(r[1]), "=r"(r[2]), "=r"(r[3])
                 : "r"(addr) : "memory");
}
__device__ __forceinline__ void ldm4t(uint32_t addr, uint32_t* r) {
    asm volatile("ldmatrix.sync.aligned.m8n8.x4.trans.shared.b16 {%0,%1,%2,%3}, [%4];"
                 : "=r"(r[0]), "=r"(r[1]), "=r"(r[2]), "=r"(r[3])
                 : "r"(addr) : "memory");
}
__device__ __forceinline__ void mma_f16(float* d, const uint32_t* a,
                                        uint32_t b0, uint32_t b1) {
    asm volatile(
        "mma.sync.aligned.m16n8k16.row.col.f32.f16.f16.f32 "
        "{%0,%1,%2,%3}, {%4,%5,%6,%7}, {%8,%9}, {%0,%1,%2,%3};"
        : "+f"(d[0]), "+f"(d[1]), "+f"(d[2]), "+f"(d[3])
        : "r"(a[0]), "r"(a[1]), "r"(a[2]), "r"(a[3]), "r"(b0), "r"(b1));
}
__device__ __forceinline__ uint32_t pack_h2(float a, float b) {
    __half2 h = __floats2half2_rn(a, b);
    return *(uint32_t*)&h;
}

// ================= merged fp32 -> fp16 convert (two tensors) =================
__global__ __launch_bounds__(256)
void f32_to_f16_dual(const float* __restrict__ X0, __half* __restrict__ O0, long n0,
                     const float* __restrict__ X1, __half* __restrict__ O1, long n1)
{
    long i = (long)blockIdx.x * blockDim.x + threadIdx.x;
    long stride = (long)gridDim.x * blockDim.x;
    long tot = n0 + n1;
    for (; i < tot; i += stride) {
        const float* X; __half* O; long j;
        if (i < n0) { X = X0; O = O0; j = i; }
        else        { X = X1; O = O1; j = i - n0; }
        float4 v = ((const float4*)X)[j];
        ((__half2*)O)[2*j]   = __floats2half2_rn(v.x, v.y);
        ((__half2*)O)[2*j+1] = __floats2half2_rn(v.z, v.w);
    }
}

// ============ all weights fp16 + transpose in one launch =====================
__global__ __launch_bounds__(256)
void wt_f16_tri(const float* __restrict__ W0, __half* __restrict__ H0,
                const float* __restrict__ W1, __half* __restrict__ H1,
                const float* __restrict__ W2, __half* __restrict__ H2)
{
    __shared__ float tile[32][33];
    const float* W = (blockIdx.z == 0) ? W0 : (blockIdx.z == 1) ? W1 : W2;
    __half* Ht     = (blockIdx.z == 0) ? H0 : (blockIdx.z == 1) ? H1 : H2;
    int tx = threadIdx.x & 31, ty = threadIdx.x >> 5;
    int nb = blockIdx.x * 32, kb = blockIdx.y * 32;
    #pragma unroll
    for (int r = ty; r < 32; r += 8)
        tile[r][tx] = W[(size_t)(kb + r) * DM + nb + tx];
    __syncthreads();
    #pragma unroll
    for (int r = ty; r < 32; r += 8)
        Ht[(size_t)(nb + r) * DM + kb + tx] = __float2half_rn(tile[tx][r]);
}

// ================= RoPE cos/sin table ========================================
__global__ __launch_bounds__(256)
void rope_tab_kernel(const float* __restrict__ fpos)
{
    const int n = blockIdx.x;
    const float px = fpos[2 * n];
    const float py = fpos[2 * n + 1];
    const float TS = -9.210340371976184f / 288.0f;
    for (int p = threadIdx.x; p < 576; p += 256) {
        int q = (p < 288) ? p : (p - 288);
        float theta = expf((float)q * TS);
        float ang = ((p < 288) ? px : py) * theta;
        float c, s;
        sincosf(ang, &s, &c);
        g_rtab[(size_t)n * 576 + p] = make_float2(c, s);
    }
}

// =================== GEMM core: BK=32, GNST=4, continuous frag pipeline ======
// Tile: 128 rows x 64B (32 fp16). chunk j of row r stored at (j ^ ((r>>1)&3))*16.
#define GTB32 8192                    // one 128x64B tile
#define GSTG32 (2 * GTB32)            // 16384 (A, B)
#define GNST 4
#define GEMM_SMEM (GNST * GSTG32)     // 65536
#define KC3 36                        // 1152 / 32

template <typename TO>
__device__ __forceinline__
void gemm_body(const __half* __restrict__ A, const __half* __restrict__ BhT,
               TO* __restrict__ C, int M, int m0, int n0, char* dsm)
{
    const int tid  = threadIdx.x;
    const int lane = tid & 31;
    const int wid  = tid >> 5;
    const int wm   = wid & 1;
    const int wn   = wid >> 1;

    uint32_t sb = smem_u32(dsm);
    const char* srcbase[2] = { (const char*)A, (const char*)BhT };

    float acc[4][8][4];
    #pragma unroll
    for (int i = 0; i < 4; i++)
        #pragma unroll
        for (int j = 0; j < 8; j++)
            #pragma unroll
            for (int q = 0; q < 4; q++) acc[i][j][q] = 0.f;

    auto load_stage = [&](int stage, int chunk) {
        uint32_t stb = sb + (uint32_t)stage * (uint32_t)GSTG32;
        #pragma unroll
        for (int it = 0; it < 8; it++) {
            int flat = tid + it * 128;          // 0..1023
            int t2 = flat >> 9;                 // 0..1
            int r  = (flat >> 2) & 127;
            int c4 = flat & 3;
            int grow;
            if (t2 == 0) { grow = m0 + r; if (grow > M - 1) grow = M - 1; }
            else         { grow = n0 + r; }
            const char* src = srcbase[t2] + (size_t)grow * (DM * 2)
                              + (size_t)chunk * 64 + c4 * 16;
            uint32_t dst = stb + (uint32_t)t2 * (uint32_t)GTB32
                           + (uint32_t)r * 64u
                           + (uint32_t)((c4 ^ ((r >> 1) & 3)) << 4);
            cp16(dst, src);
        }
        asm volatile("cp.async.commit_group;" ::: "memory");
    };

    load_stage(0, 0);
    load_stage(1, 1);
    load_stage(2, 2);

    // ldmatrix: row = base + (lane&15); logical chunk j = 2*kc + (lane>>4)
    // swizzled offset = (j ^ ((lane>>1)&3)) * 16   (row>>1 & 3 == lane>>1 & 3)
    const uint32_t lsw = (uint32_t)((lane >> 1) & 3);
    uint32_t xoff[2];
    #pragma unroll
    for (int kc = 0; kc < 2; kc++)
        xoff[kc] = (uint32_t)(((2 * kc + (lane >> 4)) ^ lsw) << 4);
    uint32_t aRow[4], bRow[4];
    #pragma unroll
    for (int i = 0; i < 4; i++) {
        aRow[i] = (uint32_t)(wm * 64 + i * 16 + (lane & 15)) * 64u;
        bRow[i] = (uint32_t)(wn * 64 + i * 16 + (lane & 15)) * 64u;
    }

    uint32_t ah[2][4][4], bh[2][4][4];
    int par = 0;

    for (int c = 0; c < KC3; c++) {
        if (c < KC3 - 3) asm volatile("cp.async.wait_group 1;" ::: "memory");
        else             asm volatile("cp.async.wait_group 0;" ::: "memory");
        __syncthreads();   // chunks <= c+1 visible to ALL threads

        if (c + 3 < KC3) load_stage((c + 3) & 3, c + 3);

        uint32_t stb = sb + (uint32_t)(c & 3) * (uint32_t)GSTG32;
        if (c == 0) {
            #pragma unroll
            for (int a = 0; a < 4; a++) ldm4(stb + aRow[a] + xoff[0], ah[0][a]);
            #pragma unroll
            for (int b = 0; b < 4; b++) ldm4(stb + GTB32 + bRow[b] + xoff[0], bh[0][b]);
            par = 0;
        }

        #pragma unroll
        for (int kc = 0; kc < 2; kc++) {
            const int cur = par, nxt = par ^ 1;
            if (kc == 0) {
                #pragma unroll
                for (int a = 0; a < 4; a++) ldm4(stb + aRow[a] + xoff[1], ah[nxt][a]);
                #pragma unroll
                for (int b = 0; b < 4; b++) ldm4(stb + GTB32 + bRow[b] + xoff[1], bh[nxt][b]);
            } else if (c + 1 < KC3) {
                // cross-chunk prefetch: chunk c+1 kc0 (stage untouched by refills
                // until iter c+2; data complete since wait guaranteed chunks <= c+1)
                uint32_t stn = sb + (uint32_t)((c + 1) & 3) * (uint32_t)GSTG32;
                #pragma unroll
                for (int a = 0; a < 4; a++) ldm4(stn + aRow[a] + xoff[0], ah[nxt][a]);
                #pragma unroll
                for (int b = 0; b < 4; b++) ldm4(stn + GTB32 + bRow[b] + xoff[0], bh[nxt][b]);
            }
            #pragma unroll
            for (int am = 0; am < 4; am++) {
                #pragma unroll
                for (int bt = 0; bt < 4; bt++) {
                    mma_f16(acc[am][2*bt],   ah[cur][am], bh[cur][bt][0], bh[cur][bt][2]);
                    mma_f16(acc[am][2*bt+1], ah[cur][am], bh[cur][bt][1], bh[cur][bt][3]);
                }
            }
            par ^= 1;
        }
    }

    #pragma unroll
    for (int am = 0; am < 4; am++) {
        int m = m0 + wm * 64 + am * 16 + (lane >> 2);
        #pragma unroll
        for (int bt = 0; bt < 8; bt++) {
            int n = n0 + wn * 64 + bt * 8 + (lane & 3) * 2;
            if (sizeof(TO) == 4) {
                if (m < M)
                    *(float2*)((float*)C + (size_t)m * DM + n) =
                        make_float2(acc[am][bt][0], acc[am][bt][1]);
                if (m + 8 < M)
                    *(float2*)((float*)C + (size_t)(m + 8) * DM + n) =
                        make_float2(acc[am][bt][2], acc[am][bt][3]);
            } else {
                if (m < M)
                    *(__half2*)((__half*)C + (size_t)m * DM + n) =
                        __floats2half2_rn(acc[am][bt][0], acc[am][bt][1]);
                if (m + 8 < M)
                    *(__half2*)((__half*)C + (size_t)(m + 8) * DM + n) =
                        __floats2half2_rn(acc[am][bt][2], acc[am][bt][3]);
            }
        }
    }
}

__global__ __launch_bounds__(128)
void gemm_qk_kernel(const __half* __restrict__ Aq, const __half* __restrict__ Bq,
                    __half* __restrict__ Cq,
                    const __half* __restrict__ Ak, const __half* __restrict__ Bk,
                    __half* __restrict__ Ck)
{
    extern __shared__ char dsm[];
    const int n0 = blockIdx.x * 128;
    if (blockIdx.y < MQB)
        gemm_body<__half>(Aq, Bq, Cq, MQ, blockIdx.y * 128, n0, dsm);
    else
        gemm_body<__half>(Ak, Bk, Ck, MK, (blockIdx.y - MQB) * 128, n0, dsm);
}

__global__ __launch_bounds__(128)
void gemm_out_kernel(const __half* __restrict__ A, const __half* __restrict__ B,
                     float* __restrict__ C, int M)
{
    extern __shared__ char dsm[];
    gemm_body<float>(A, B, C, M, blockIdx.y * 128, blockIdx.x * 128, dsm);
}

// ---------------- register-resident merged LN(Q) + RoPE+LN(K) ----------------
__global__ __launch_bounds__(192)
void ln_all_kernel(const __half* __restrict__ Qg, const float* __restrict__ qw,
                   __half* __restrict__ Qo,
                   const __half* __restrict__ Kg, const float* __restrict__ kw,
                   __half* __restrict__ Ko)
{
    __shared__ float red[14];
    const int b = blockIdx.x;
    const bool isQ = (b < MQ);
    const int row = isQ ? b : (b - MQ);
    const __half2* x2 = (const __half2*)((isQ ? Qg : Kg) + (size_t)row * DM);
    const float2* w2 = (const float2*)(isQ ? qw : kw);
    __half2* o2 = (__half2*)((isQ ? Qo : Ko) + (size_t)row * DM);
    const int tid = threadIdx.x;

    float vx[3][2];
    if (isQ) {
        #pragma unroll
        for (int r = 0; r < 3; r++) {
            __half2 v = x2[tid + r * 192];
            vx[r][0] = __low2float(v);
            vx[r][1] = __high2float(v);
        }
    } else {
        const float2* rt = g_rtab + (size_t)(row % HW_DIM) * 576;
        #pragma unroll
        for (int r = 0; r < 3; r++) {
            int j = tid + r * 192;
            __half2 v = x2[j];
            float2 cs = rt[j];
            float a = __low2float(v), bb = __high2float(v);
            vx[r][0] = a * cs.x - bb * cs.y;
            vx[r][1] = a * cs.y + bb * cs.x;
        }
    }
    float s = 0.f, ss = 0.f;
    #pragma unroll
    for (int r = 0; r < 3; r++) {
        s  += vx[r][0] + vx[r][1];
        ss += vx[r][0] * vx[r][0] + vx[r][1] * vx[r][1];
    }
    #pragma unroll
    for (int o = 16; o; o >>= 1) {
        s  += __shfl_down_sync(0xffffffffu, s, o);
        ss += __shfl_down_sync(0xffffffffu, ss, o);
    }
    int wid = tid >> 5, lane = tid & 31;
    if (lane == 0) { red[wid] = s; red[6 + wid] = ss; }
    __syncthreads();
    if (tid == 0) {
        float S = 0.f, SS = 0.f;
        #pragma unroll
        for (int i = 0; i < 6; i++) { S += red[i]; SS += red[6 + i]; }
        red[12] = S; red[13] = SS;
    }
    __syncthreads();
    float mu  = red[12] * (1.f / DM);
    float var = red[13] * (1.f / DM) - mu * mu;
    float inv = rsqrtf(var + 1e-6f);
    #pragma unroll
    for (int r = 0; r < 3; r++) {
        int j = tid + r * 192;
        float2 w = w2[j];
        o2[j] = __floats2half2_rn((vx[r][0] - mu) * inv * w.x,
                                  (vx[r][1] - mu) * inv * w.y);
    }
}

// ---------------- tensor-core fused attention ---------------------------------
#define APITCH 304
#define ATSZ   (64 * APITCH)
#define ASTG   (2 * ATSZ)
#define ANST   3
#define AKPOS  (ANST * ASTG)
#define ATTN_SMEM (AKPOS + ANST * 512)

__global__ __launch_bounds__(256, 1)
void attn_mma_kernel(const __half* __restrict__ Qh, const __half* __restrict__ Kh,
                     const __half* __restrict__ Vh,
                     const float* __restrict__ tracks, const float* __restrict__ fpos,
                     __half* __restrict__ Sh)
{
    extern __shared__ char sm[];
    uint32_t sb = smem_u32(sm);
    const int tid  = threadIdx.x;
    const int lane = tid & 31;
    const int w    = tid >> 5;
    const int gid  = lane >> 2;
    const int tig  = lane & 3;
    const int m0   = blockIdx.x * 128;
    const int h    = blockIdx.y;
    const int t    = blockIdx.z;

    const char* qbase  = (const char*)(Qh + ((size_t)t * M_TRK + m0) * DM + h * DH);
    const char* khbase = (const char*)(Kh + (size_t)t * HW_DIM * DM + h * DH);
    const char* vbase  = (const char*)(Vh + (size_t)t * HW_DIM * DM + h * DH);

    float2 qp0 = *(const float2*)(tracks + ((size_t)t * M_TRK + m0 + w * 16 + gid) * 2);
    float2 qp1 = *(const float2*)(tracks + ((size_t)t * M_TRK + m0 + w * 16 + gid + 8) * 2);

    #pragma unroll
    for (int i = 0; i < 9; i++) {
        int c = tid + i * 256;
        int row = c / 18, ch = c % 18;
        cp16(sb + row * APITCH + ch * 16, qbase + (size_t)row * (DM * 2) + ch * 16);
    }
    asm volatile("cp.async.commit_group;" ::: "memory");
    asm volatile("cp.async.wait_group 0;" ::: "memory");
    __syncthreads();

    uint32_t qf[9][4];
    {
        uint32_t qa = sb + (uint32_t)(w * 16 + (lane & 15)) * APITCH + (uint32_t)(lane >> 4) * 16u;
        #pragma unroll
        for (int kc = 0; kc < 9; kc++) ldm4(qa + kc * 32, qf[kc]);
    }
    __syncthreads();

    auto load_tile = [&](int st, int kt) {
        int k0 = kt * 64;
        uint32_t stb = sb + (uint32_t)st * (uint32_t)ASTG;
        #pragma unroll
        for (int i = 0; i < 9; i++) {
            int c = tid + i * 256;
            int buf = c / 1152, rem = c % 1152;
            int row = rem / 18, ch = rem % 18;
            int krow = k0 + row; if (krow > HW_DIM - 1) krow = HW_DIM - 1;
            const char* src = (buf == 0) ? khbase : vbase;
            cp16(stb + (uint32_t)buf * (uint32_t)ATSZ + (uint32_t)row * APITCH + (uint32_t)ch * 16u,
                 src + (size_t)krow * (DM * 2) + ch * 16);
        }
        asm volatile("cp.async.commit_group;" ::: "memory");
        if (tid < 64) {
            int kr = k0 + tid; if (kr > HW_DIM - 1) kr = HW_DIM - 1;
            float2 v = *(const float2*)(fpos + (size_t)kr * 2);
            *(float2*)(sm + AKPOS + st * 512 + tid * 8) = v;
        }
    };

    load_tile(0, 0);
    load_tile(1, 1);

    float m_0 = -1e30f, m_1 = -1e30f, l_0 = 0.f, l_1 = 0.f;
    float oacc[18][4];
    #pragma unroll
    for (int a = 0; a < 18; a++)
        #pragma unroll
        for (int q = 0; q < 4; q++) oacc[a][q] = 0.f;

    const int NT = (HW_DIM + 63) / 64;   // 12
    for (int kt = 0; kt < NT; kt++) {
        const int st = kt % ANST;
        const int k0 = kt * 64;
        const int cnt = min(64, HW_DIM - k0);
        if (kt < NT - 1) asm volatile("cp.async.wait_group 1;" ::: "memory");
        else             asm volatile("cp.async.wait_group 0;" ::: "memory");
        __syncthreads();

        if (kt + 2 < NT) load_tile((kt + 2) % ANST, kt + 2);

        uint32_t stb = sb + (uint32_t)st * (uint32_t)ASTG;
        uint32_t lrow = (uint32_t)(lane & 15) * APITCH + (uint32_t)(lane >> 4) * 16u;
        uint32_t khb = stb + lrow;
        uint32_t vhb = stb + ATSZ + lrow;

        float sacc[8][4];
        #pragma unroll
        for (int a = 0; a < 8; a++)
            #pragma unroll
            for (int q = 0; q < 4; q++) sacc[a][q] = 0.f;

        uint32_t bhf[2][4][4];
        #pragma unroll
        for (int g = 0; g < 4; g++) ldm4(khb + g * (16 * APITCH), bhf[0][g]);
        #pragma unroll
        for (int kc = 0; kc < 9; kc++) {
            const int cur = kc & 1, nxt = cur ^ 1;
            if (kc < 8) {
                #pragma unroll
                for (int g = 0; g < 4; g++)
                    ldm4(khb + g * (16 * APITCH) + (kc + 1) * 32, bhf[nxt][g]);
            }
            #pragma unroll
            for (int g = 0; g < 4; g++) {
                mma_f16(sacc[2*g],   qf[kc], bhf[cur][g][0], bhf[cur][g][2]);
                mma_f16(sacc[2*g+1], qf[kc], bhf[cur][g][1], bhf[cur][g][3]);
            }
        }

        const float2* kp = (const float2*)(sm + AKPOS + st * 512);
        float mn0 = m_0, mn1 = m_1;
        #pragma unroll
        for (int a = 0; a < 8; a++) {
            int c0 = a * 8 + tig * 2;
            float2 ka = kp[c0];
            float2 kb = kp[c0 + 1];
            float dxa0 = qp0.x - ka.x, dya0 = qp0.y - ka.y;
            float dxb0 = qp0.x - kb.x, dyb0 = qp0.y - kb.y;
            float dxa1 = qp1.x - ka.x, dya1 = qp1.y - ka.y;
            float dxb1 = qp1.x - kb.x, dyb1 = qp1.y - kb.y;
            bool va = (c0 < cnt), vb = (c0 + 1 < cnt);
            sacc[a][0] = va ? sacc[a][0] * (1.f/12.f) - (dxa0*dxa0 + dya0*dya0) * 0.125f : -1e30f;
            sacc[a][1] = vb ? sacc[a][1] * (1.f/12.f) - (dxb0*dxb0 + dyb0*dyb0) * 0.125f : -1e30f;
            sacc[a][2] = va ? sacc[a][2] * (1.f/12.f) - (dxa1*dxa1 + dya1*dya1) * 0.125f : -1e30f;
            sacc[a][3] = vb ? sacc[a][3] * (1.f/12.f) - (dxb1*dxb1 + dyb1*dyb1) * 0.125f : -1e30f;
            mn0 = fmaxf(mn0, fmaxf(sacc[a][0], sacc[a][1]));
            mn1 = fmaxf(mn1, fmaxf(sacc[a][2], sacc[a][3]));
        }
        mn0 = fmaxf(mn0, __shfl_xor_sync(0xffffffffu, mn0, 1));
        mn0 = fmaxf(mn0, __shfl_xor_sync(0xffffffffu, mn0, 2));
        mn1 = fmaxf(mn1, __shfl_xor_sync(0xffffffffu, mn1, 1));
        mn1 = fmaxf(mn1, __shfl_xor_sync(0xffffffffu, mn1, 2));
        float corr0 = __expf(m_0 - mn0);
        float corr1 = __expf(m_1 - mn1);
        m_0 = mn0; m_1 = mn1;
        l_0 *= corr0; l_1 *= corr1;
        #pragma unroll
        for (int a = 0; a < 18; a++) {
            oacc[a][0] *= corr0; oacc[a][1] *= corr0;
            oacc[a][2] *= corr1; oacc[a][3] *= corr1;
        }
        #pragma unroll
        for (int a = 0; a < 8; a++) {
            float p0 = __expf(sacc[a][0] - m_0);
            float p1 = __expf(sacc[a][1] - m_0);
            float p2 = __expf(sacc[a][2] - m_1);
            float p3 = __expf(sacc[a][3] - m_1);
            l_0 += p0 + p1; l_1 += p2 + p3;
            sacc[a][0] = p0; sacc[a][1] = p1; sacc[a][2] = p2; sacc[a][3] = p3;
        }

        #pragma unroll
        for (int kc4 = 0; kc4 < 4; kc4++) {
            uint32_t pa[4];
            pa[0] = pack_h2(sacc[2*kc4][0],   sacc[2*kc4][1]);
            pa[1] = pack_h2(sacc[2*kc4][2],   sacc[2*kc4][3]);
            pa[2] = pack_h2(sacc[2*kc4+1][0], sacc[2*kc4+1][1]);
            pa[3] = pack_h2(sacc[2*kc4+1][2], sacc[2*kc4+1][3]);
            uint32_t vf[2][4];
            ldm4t(vhb + kc4 * (16 * APITCH), vf[0]);
            #pragma unroll
            for (int dp = 0; dp < 9; dp++) {
                const int cur = dp & 1, nxt = cur ^ 1;
                if (dp < 8)
                    ldm4t(vhb + kc4 * (16 * APITCH) + (dp + 1) * 32, vf[nxt]);
                mma_f16(oacc[2*dp],   pa, vf[cur][0], vf[cur][1]);
                mma_f16(oacc[2*dp+1], pa, vf[cur][2], vf[cur][3]);
            }
        }
    }

    l_0 += __shfl_xor_sync(0xffffffffu, l_0, 1);
    l_0 += __shfl_xor_sync(0xffffffffu, l_0, 2);
    l_1 += __shfl_xor_sync(0xffffffffu, l_1, 1);
    l_1 += __shfl_xor_sync(0xffffffffu, l_1, 2);
    float inv0 = 1.f / l_0, inv1 = 1.f / l_1;

    size_t row0 = (size_t)t * M_TRK + m0 + w * 16 + gid;
    #pragma unroll
    for (int a = 0; a < 18; a++) {
        int col = h * DH + a * 8 + tig * 2;
        *(__half2*)(Sh + row0 * DM + col) =
            __floats2half2_rn(oacc[a][0] * inv0, oacc[a][1] * inv0);
        *(__half2*)(Sh + (row0 + 8) * DM + col) =
            __floats2half2_rn(oacc[a][2] * inv1, oacc[a][3] * inv1);
    }
}

// ---------------- launch ----------------
extern "C" void kernel_launch(void* const* d_in, const int* in_sizes, int n_in,
                              void* d_out, int out_size)
{
    const float* features    = (const float*)d_in[0];
    const float* tracks      = (const float*)d_in[1];
    const float* track_toks  = (const float*)d_in[2];
    const float* fpos        = (const float*)d_in[3];
    const float* W_q         = (const float*)d_in[4];
    const float* W_k         = (const float*)d_in[5];
    const float* q_norm_w    = (const float*)d_in[6];
    const float* k_norm_w    = (const float*)d_in[7];
    const float* out_proj_w  = (const float*)d_in[8];
    float* out = (float*)d_out;

    __half *gQg, *gKg, *gTTh, *gFh, *gWq, *gWk, *gWo, *gQh, *gKh, *gSh;
    cudaGetSymbolAddress((void**)&gQg, g_Qg);
    cudaGetSymbolAddress((void**)&gKg, g_Kg);
    cudaGetSymbolAddress((void**)&gTTh, g_TTh);
    cudaGetSymbolAddress((void**)&gFh, g_Fh);
    cudaGetSymbolAddress((void**)&gWq, g_Wq);
    cudaGetSymbolAddress((void**)&gWk, g_Wk);
    cudaGetSymbolAddress((void**)&gWo, g_Wo);
    cudaGetSymbolAddress((void**)&gQh, g_Qh);
    cudaGetSymbolAddress((void**)&gKh, g_Kh);
    cudaGetSymbolAddress((void**)&gSh, g_Sh);

    cudaFuncSetAttribute(gemm_qk_kernel,
                         cudaFuncAttributeMaxDynamicSharedMemorySize, GEMM_SMEM);
    cudaFuncSetAttribute(gemm_out_kernel,
                         cudaFuncAttributeMaxDynamicSharedMemorySize, GEMM_SMEM);
    cudaFuncSetAttribute(attn_mma_kernel,
                         cudaFuncAttributeMaxDynamicSharedMemorySize, ATTN_SMEM);

    // ---- fused converts + all weight tables + RoPE table ----
    f32_to_f16_dual<<<4096, 256>>>(track_toks, gTTh, (long)MQ * DM / 4,
                                   features, gFh, (long)MK * DM / 4);
    {
        dim3 g(DM / 32, DM / 32, 3);
        wt_f16_tri<<<g, 256>>>(W_q, gWq, W_k, gWk, out_proj_w, gWo);
    }
    rope_tab_kernel<<<HW_DIM, 256>>>(fpos);

    // ---- merged Q + K GEMM ----
    {
        dim3 g(DM / 128, MQB + MKB);
        gemm_qk_kernel<<<g, 128, GEMM_SMEM>>>(gTTh, gWq, gQg, gFh, gWk, gKg);
    }

    // ---- merged register-resident LN(Q) + RoPE+LN(K) ----
    ln_all_kernel<<<MQ + MK, 192>>>(gQg, q_norm_w, gQh, gKg, k_norm_w, gKh);

    // ---- fused tensor-core attention (V = features fp16) ----
    {
        dim3 g(M_TRK / 128, NH, T_DIM);
        attn_mma_kernel<<<g, 256, ATTN_SMEM>>>(gQh, gKh, gFh, tracks, fpos, gSh);
    }

    // ---- out = sampled @ out_proj_w (fp32 out) ----
    {
        dim3 g(DM / 128, MQB);
        gemm_out_kernel<<<g, 128, GEMM_SMEM>>>(gSh, gWo, out, MQ);
    }
}

// round 15
// speedup vs baseline: 1.1307x; 1.1307x over previous
#include <cuda_runtime.h>
#include <cuda_fp16.h>
#include <math.h>
#include <stdint.h>

// ---------------- problem constants ----------------
#define T_DIM   64
#define HW_DIM  729
#define M_TRK   512
#define DM      1152
#define NH      8
#define DH      144
#define MQ      (T_DIM * M_TRK)    // 32768
#define MK      (T_DIM * HW_DIM)   // 46656
#define MQB     (MQ / 128)         // 256
#define MKB     ((MK + 127) / 128) // 365

// ---------------- device scratch ----------------
__device__ __half g_Qg[(size_t)MQ * DM];
__device__ __half g_Kg[(size_t)MK * DM];
__device__ __half g_TTh[(size_t)MQ * DM];
__device__ __half g_Fh[(size_t)MK * DM];
__device__ __half g_Wq[(size_t)DM * DM];
__device__ __half g_Wk[(size_t)DM * DM];
__device__ __half g_Wo[(size_t)DM * DM];
__device__ __half g_Qh[(size_t)MQ * DM];
__device__ __half g_Kh[(size_t)MK * DM];
__device__ __half g_Sh[(size_t)MQ * DM];
__device__ float2 g_rtab[(size_t)HW_DIM * 576];

__device__ __forceinline__ uint32_t smem_u32(const void* p) {
    uint32_t a;
    asm("{ .reg .u64 t; cvta.to.shared.u64 t, %1; cvt.u32.u64 %0, t; }" : "=r"(a) : "l"(p));
    return a;
}
__device__ __forceinline__ void cp16(uint32_t dst, const void* src) {
    asm volatile("cp.async.cg.shared.global [%0], [%1], 16;" :: "r"(dst), "l"(src));
}
__device__ __forceinline__ void ldm4(uint32_t addr, uint32_t* r) {
    asm volatile("ldmatrix.sync.aligned.m8n8.x4.shared.b16 {%0,%1,%2,%3}, [%4];"
                 : "=r"(r[0]), "=r"(r[1]), "=r"(r[2]), "=r"(r[3])
                 : "r"(addr) : "memory");
}
__device__ __forceinline__ void ldm4t(uint32_t addr, uint32_t* r) {
    asm volatile("ldmatrix.sync.aligned.m8n8.x4.trans.shared.b16 {%0,%1,%2,%3}, [%4];"
                 : "=r"(r[0]), "=r"(r[1]), "=r"(r[2]), "=r"(r[3])
                 : "r"(addr) : "memory");
}
__device__ __forceinline__ void mma_f16(float* d, const uint32_t* a,
                                        uint32_t b0, uint32_t b1) {
    asm volatile(
        "mma.sync.aligned.m16n8k16.row.col.f32.f16.f16.f32 "
        "{%0,%1,%2,%3}, {%4,%5,%6,%7}, {%8,%9}, {%0,%1,%2,%3};"
        : "+f"(d[0]), "+f"(d[1]), "+f"(d[2]), "+f"(d[3])
        : "r"(a[0]), "r"(a[1]), "r"(a[2]), "r"(a[3]), "r"(b0), "r"(b1));
}
__device__ __forceinline__ uint32_t pack_h2(float a, float b) {
    __half2 h = __floats2half2_rn(a, b);
    return *(uint32_t*)&h;
}

// ================= merged fp32 -> fp16 convert (two tensors) =================
__global__ __launch_bounds__(256)
void f32_to_f16_dual(const float* __restrict__ X0, __half* __restrict__ O0, long n0,
                     const float* __restrict__ X1, __half* __restrict__ O1, long n1)
{
    long i = (long)blockIdx.x * blockDim.x + threadIdx.x;
    long stride = (long)gridDim.x * blockDim.x;
    long tot = n0 + n1;
    for (; i < tot; i += stride) {
        const float* X; __half* O; long j;
        if (i < n0) { X = X0; O = O0; j = i; }
        else        { X = X1; O = O1; j = i - n0; }
        float4 v = ((const float4*)X)[j];
        ((__half2*)O)[2*j]   = __floats2half2_rn(v.x, v.y);
        ((__half2*)O)[2*j+1] = __floats2half2_rn(v.z, v.w);
    }
}

// ============ all weights fp16 + transpose in one launch =====================
__global__ __launch_bounds__(256)
void wt_f16_tri(const float* __restrict__ W0, __half* __restrict__ H0,
                const float* __restrict__ W1, __half* __restrict__ H1,
                const float* __restrict__ W2, __half* __restrict__ H2)
{
    __shared__ float tile[32][33];
    const float* W = (blockIdx.z == 0) ? W0 : (blockIdx.z == 1) ? W1 : W2;
    __half* Ht     = (blockIdx.z == 0) ? H0 : (blockIdx.z == 1) ? H1 : H2;
    int tx = threadIdx.x & 31, ty = threadIdx.x >> 5;
    int nb = blockIdx.x * 32, kb = blockIdx.y * 32;
    #pragma unroll
    for (int r = ty; r < 32; r += 8)
        tile[r][tx] = W[(size_t)(kb + r) * DM + nb + tx];
    __syncthreads();
    #pragma unroll
    for (int r = ty; r < 32; r += 8)
        Ht[(size_t)(nb + r) * DM + kb + tx] = __float2half_rn(tile[tx][r]);
}

// ================= RoPE cos/sin table ========================================
__global__ __launch_bounds__(256)
void rope_tab_kernel(const float* __restrict__ fpos)
{
    const int n = blockIdx.x;
    const float px = fpos[2 * n];
    const float py = fpos[2 * n + 1];
    const float TS = -9.210340371976184f / 288.0f;
    for (int p = threadIdx.x; p < 576; p += 256) {
        int q = (p < 288) ? p : (p - 288);
        float theta = expf((float)q * TS);
        float ang = ((p < 288) ? px : py) * theta;
        float c, s;
        sincosf(ang, &s, &c);
        g_rtab[(size_t)n * 576 + p] = make_float2(c, s);
    }
}

// =================== GEMM core (R13: BK=64, GNST=3, XOR swizzle) =============
#define GTB 16384
#define GSTG (2 * GTB)
#define GNST 3
#define GEMM_SMEM (GNST * GSTG)       // 98304
#define KC2 18

template <typename TO>
__device__ __forceinline__
void gemm_body(const __half* __restrict__ A, const __half* __restrict__ BhT,
               TO* __restrict__ C, int M, int m0, int n0, char* dsm)
{
    const int tid  = threadIdx.x;
    const int lane = tid & 31;
    const int wid  = tid >> 5;
    const int wm   = wid & 1;
    const int wn   = wid >> 1;

    uint32_t sb = smem_u32(dsm);
    const char* srcbase[2] = { (const char*)A, (const char*)BhT };

    float acc[4][8][4];
    #pragma unroll
    for (int i = 0; i < 4; i++)
        #pragma unroll
        for (int j = 0; j < 8; j++)
            #pragma unroll
            for (int q = 0; q < 4; q++) acc[i][j][q] = 0.f;

    auto load_stage = [&](int stage, int chunk) {
        uint32_t stb = sb + (uint32_t)stage * (uint32_t)GSTG;
        #pragma unroll
        for (int it = 0; it < 16; it++) {
            int flat = tid + it * 128;
            int t2 = flat >> 10;
            int r  = (flat >> 3) & 127;
            int c4 = flat & 7;
            int grow;
            if (t2 == 0) { grow = m0 + r; if (grow > M - 1) grow = M - 1; }
            else         { grow = n0 + r; }
            const char* src = srcbase[t2] + (size_t)grow * (DM * 2)
                              + (size_t)chunk * 128 + c4 * 16;
            uint32_t dst = stb + (uint32_t)t2 * (uint32_t)GTB
                           + (uint32_t)r * 128u + (uint32_t)((c4 ^ (r & 7)) << 4);
            cp16(dst, src);
        }
        asm volatile("cp.async.commit_group;" ::: "memory");
    };

    load_stage(0, 0);
    load_stage(1, 1);

    uint32_t xoff[4];
    #pragma unroll
    for (int kc = 0; kc < 4; kc++)
        xoff[kc] = (uint32_t)(((2 * kc + (lane >> 4)) ^ (lane & 7)) << 4);
    uint32_t aRow[4], bRow[4];
    #pragma unroll
    for (int i = 0; i < 4; i++) {
        aRow[i] = (uint32_t)(wm * 64 + i * 16 + (lane & 15)) * 128u;
        bRow[i] = (uint32_t)(wn * 64 + i * 16 + (lane & 15)) * 128u;
    }

    uint32_t ah[2][4][4], bh[2][4][4];

    for (int c = 0; c < KC2; c++) {
        const int s = c % GNST;
        if (c < KC2 - 1) asm volatile("cp.async.wait_group 1;" ::: "memory");
        else             asm volatile("cp.async.wait_group 0;" ::: "memory");
        __syncthreads();

        if (c + 2 < KC2) load_stage((c + 2) % GNST, c + 2);

        uint32_t stb = sb + (uint32_t)s * (uint32_t)GSTG;

        #pragma unroll
        for (int a = 0; a < 4; a++) ldm4(stb + aRow[a] + xoff[0], ah[0][a]);
        #pragma unroll
        for (int b = 0; b < 4; b++) ldm4(stb + GTB + bRow[b] + xoff[0], bh[0][b]);

        #pragma unroll
        for (int kc = 0; kc < 4; kc++) {
            const int cur = kc & 1, nxt = cur ^ 1;
            if (kc < 3) {
                #pragma unroll
                for (int a = 0; a < 4; a++) ldm4(stb + aRow[a] + xoff[kc+1], ah[nxt][a]);
                #pragma unroll
                for (int b = 0; b < 4; b++) ldm4(stb + GTB + bRow[b] + xoff[kc+1], bh[nxt][b]);
            }
            #pragma unroll
            for (int am = 0; am < 4; am++) {
                #pragma unroll
                for (int bt = 0; bt < 4; bt++) {
                    mma_f16(acc[am][2*bt],   ah[cur][am], bh[cur][bt][0], bh[cur][bt][2]);
                    mma_f16(acc[am][2*bt+1], ah[cur][am], bh[cur][bt][1], bh[cur][bt][3]);
                }
            }
        }
    }

    #pragma unroll
    for (int am = 0; am < 4; am++) {
        int m = m0 + wm * 64 + am * 16 + (lane >> 2);
        #pragma unroll
        for (int bt = 0; bt < 8; bt++) {
            int n = n0 + wn * 64 + bt * 8 + (lane & 3) * 2;
            if (sizeof(TO) == 4) {
                if (m < M)
                    *(float2*)((float*)C + (size_t)m * DM + n) =
                        make_float2(acc[am][bt][0], acc[am][bt][1]);
                if (m + 8 < M)
                    *(float2*)((float*)C + (size_t)(m + 8) * DM + n) =
                        make_float2(acc[am][bt][2], acc[am][bt][3]);
            } else {
                if (m < M)
                    *(__half2*)((__half*)C + (size_t)m * DM + n) =
                        __floats2half2_rn(acc[am][bt][0], acc[am][bt][1]);
                if (m + 8 < M)
                    *(__half2*)((__half*)C + (size_t)(m + 8) * DM + n) =
                        __floats2half2_rn(acc[am][bt][2], acc[am][bt][3]);
            }
        }
    }
}

__global__ __launch_bounds__(128)
void gemm_qk_kernel(const __half* __restrict__ Aq, const __half* __restrict__ Bq,
                    __half* __restrict__ Cq,
                    const __half* __restrict__ Ak, const __half* __restrict__ Bk,
                    __half* __restrict__ Ck)
{
    extern __shared__ char dsm[];
    const int n0 = blockIdx.x * 128;
    if (blockIdx.y < MQB)
        gemm_body<__half>(Aq, Bq, Cq, MQ, blockIdx.y * 128, n0, dsm);
    else
        gemm_body<__half>(Ak, Bk, Ck, MK, (blockIdx.y - MQB) * 128, n0, dsm);
}

__global__ __launch_bounds__(128)
void gemm_out_kernel(const __half* __restrict__ A, const __half* __restrict__ B,
                     float* __restrict__ C, int M)
{
    extern __shared__ char dsm[];
    gemm_body<float>(A, B, C, M, blockIdx.y * 128, blockIdx.x * 128, dsm);
}

// ---------------- register-resident merged LN(Q) + RoPE+LN(K) ----------------
__global__ __launch_bounds__(192)
void ln_all_kernel(const __half* __restrict__ Qg, const float* __restrict__ qw,
                   __half* __restrict__ Qo,
                   const __half* __restrict__ Kg, const float* __restrict__ kw,
                   __half* __restrict__ Ko)
{
    __shared__ float red[14];
    const int b = blockIdx.x;
    const bool isQ = (b < MQ);
    const int row = isQ ? b : (b - MQ);
    const __half2* x2 = (const __half2*)((isQ ? Qg : Kg) + (size_t)row * DM);
    const float2* w2 = (const float2*)(isQ ? qw : kw);
    __half2* o2 = (__half2*)((isQ ? Qo : Ko) + (size_t)row * DM);
    const int tid = threadIdx.x;

    float vx[3][2];
    if (isQ) {
        #pragma unroll
        for (int r = 0; r < 3; r++) {
            __half2 v = x2[tid + r * 192];
            vx[r][0] = __low2float(v);
            vx[r][1] = __high2float(v);
        }
    } else {
        const float2* rt = g_rtab + (size_t)(row % HW_DIM) * 576;
        #pragma unroll
        for (int r = 0; r < 3; r++) {
            int j = tid + r * 192;
            __half2 v = x2[j];
            float2 cs = rt[j];
            float a = __low2float(v), bb = __high2float(v);
            vx[r][0] = a * cs.x - bb * cs.y;
            vx[r][1] = a * cs.y + bb * cs.x;
        }
    }
    float s = 0.f, ss = 0.f;
    #pragma unroll
    for (int r = 0; r < 3; r++) {
        s  += vx[r][0] + vx[r][1];
        ss += vx[r][0] * vx[r][0] + vx[r][1] * vx[r][1];
    }
    #pragma unroll
    for (int o = 16; o; o >>= 1) {
        s  += __shfl_down_sync(0xffffffffu, s, o);
        ss += __shfl_down_sync(0xffffffffu, ss, o);
    }
    int wid = tid >> 5, lane = tid & 31;
    if (lane == 0) { red[wid] = s; red[6 + wid] = ss; }
    __syncthreads();
    if (tid == 0) {
        float S = 0.f, SS = 0.f;
        #pragma unroll
        for (int i = 0; i < 6; i++) { S += red[i]; SS += red[6 + i]; }
        red[12] = S; red[13] = SS;
    }
    __syncthreads();
    float mu  = red[12] * (1.f / DM);
    float var = red[13] * (1.f / DM) - mu * mu;
    float inv = rsqrtf(var + 1e-6f);
    #pragma unroll
    for (int r = 0; r < 3; r++) {
        int j = tid + r * 192;
        float2 w = w2[j];
        o2[j] = __floats2half2_rn((vx[r][0] - mu) * inv * w.x,
                                  (vx[r][1] - mu) * inv * w.y);
    }
}

// ---------------- tensor-core fused attention (log2 softmax, vote rescale) ---
#define APITCH 304
#define ATSZ   (64 * APITCH)
#define ASTG   (2 * ATSZ)
#define ANST   3
#define AKPOS  (ANST * ASTG)
#define ATTN_SMEM (AKPOS + ANST * 512)

// log2(e) scalings: softmax with exp2 of (log2e * x) is exactly softmax of x.
#define SC_QK   0.1202245867f   // log2(e) / 12
#define SC_BIAS 0.1803368801f   // log2(e) / 8

__global__ __launch_bounds__(256, 1)
void attn_mma_kernel(const __half* __restrict__ Qh, const __half* __restrict__ Kh,
                     const __half* __restrict__ Vh,
                     const float* __restrict__ tracks, const float* __restrict__ fpos,
                     __half* __restrict__ Sh)
{
    extern __shared__ char sm[];
    uint32_t sb = smem_u32(sm);
    const int tid  = threadIdx.x;
    const int lane = tid & 31;
    const int w    = tid >> 5;
    const int gid  = lane >> 2;
    const int tig  = lane & 3;
    const int m0   = blockIdx.x * 128;
    const int h    = blockIdx.y;
    const int t    = blockIdx.z;

    const char* qbase  = (const char*)(Qh + ((size_t)t * M_TRK + m0) * DM + h * DH);
    const char* khbase = (const char*)(Kh + (size_t)t * HW_DIM * DM + h * DH);
    const char* vbase  = (const char*)(Vh + (size_t)t * HW_DIM * DM + h * DH);

    float2 qp0 = *(const float2*)(tracks + ((size_t)t * M_TRK + m0 + w * 16 + gid) * 2);
    float2 qp1 = *(const float2*)(tracks + ((size_t)t * M_TRK + m0 + w * 16 + gid + 8) * 2);

    #pragma unroll
    for (int i = 0; i < 9; i++) {
        int c = tid + i * 256;
        int row = c / 18, ch = c % 18;
        cp16(sb + row * APITCH + ch * 16, qbase + (size_t)row * (DM * 2) + ch * 16);
    }
    asm volatile("cp.async.commit_group;" ::: "memory");
    asm volatile("cp.async.wait_group 0;" ::: "memory");
    __syncthreads();

    uint32_t qf[9][4];
    {
        uint32_t qa = sb + (uint32_t)(w * 16 + (lane & 15)) * APITCH + (uint32_t)(lane >> 4) * 16u;
        #pragma unroll
        for (int kc = 0; kc < 9; kc++) ldm4(qa + kc * 32, qf[kc]);
    }
    __syncthreads();

    auto load_tile = [&](int st, int kt) {
        int k0 = kt * 64;
        uint32_t stb = sb + (uint32_t)st * (uint32_t)ASTG;
        #pragma unroll
        for (int i = 0; i < 9; i++) {
            int c = tid + i * 256;
            int buf = c / 1152, rem = c % 1152;
            int row = rem / 18, ch = rem % 18;
            int krow = k0 + row; if (krow > HW_DIM - 1) krow = HW_DIM - 1;
            const char* src = (buf == 0) ? khbase : vbase;
            cp16(stb + (uint32_t)buf * (uint32_t)ATSZ + (uint32_t)row * APITCH + (uint32_t)ch * 16u,
                 src + (size_t)krow * (DM * 2) + ch * 16);
        }
        asm volatile("cp.async.commit_group;" ::: "memory");
        if (tid < 64) {
            int kr = k0 + tid;
            float2 v = (kr < HW_DIM) ? *(const float2*)(fpos + (size_t)kr * 2)
                                     : make_float2(1e5f, 1e5f);   // sentinel: bias kills it
            *(float2*)(sm + AKPOS + st * 512 + tid * 8) = v;
        }
    };

    load_tile(0, 0);
    load_tile(1, 1);

    float m_0 = -1e30f, m_1 = -1e30f, l_0 = 0.f, l_1 = 0.f;
    float oacc[18][4];
    #pragma unroll
    for (int a = 0; a < 18; a++)
        #pragma unroll
        for (int q = 0; q < 4; q++) oacc[a][q] = 0.f;

    const int NT = (HW_DIM + 63) / 64;   // 12
    for (int kt = 0; kt < NT; kt++) {
        const int st = kt % ANST;
        if (kt < NT - 1) asm volatile("cp.async.wait_group 1;" ::: "memory");
        else             asm volatile("cp.async.wait_group 0;" ::: "memory");
        __syncthreads();

        if (kt + 2 < NT) load_tile((kt + 2) % ANST, kt + 2);

        uint32_t stb = sb + (uint32_t)st * (uint32_t)ASTG;
        uint32_t lrow = (uint32_t)(lane & 15) * APITCH + (uint32_t)(lane >> 4) * 16u;
        uint32_t khb = stb + lrow;
        uint32_t vhb = stb + ATSZ + lrow;

        float sacc[8][4];
        #pragma unroll
        for (int a = 0; a < 8; a++)
            #pragma unroll
            for (int q = 0; q < 4; q++) sacc[a][q] = 0.f;

        uint32_t bhf[2][4][4];
        #pragma unroll
        for (int g = 0; g < 4; g++) ldm4(khb + g * (16 * APITCH), bhf[0][g]);
        #pragma unroll
        for (int kc = 0; kc < 9; kc++) {
            const int cur = kc & 1, nxt = cur ^ 1;
            if (kc < 8) {
                #pragma unroll
                for (int g = 0; g < 4; g++)
                    ldm4(khb + g * (16 * APITCH) + (kc + 1) * 32, bhf[nxt][g]);
            }
            #pragma unroll
            for (int g = 0; g < 4; g++) {
                mma_f16(sacc[2*g],   qf[kc], bhf[cur][g][0], bhf[cur][g][2]);
                mma_f16(sacc[2*g+1], qf[kc], bhf[cur][g][1], bhf[cur][g][3]);
            }
        }

        // ---- bias (log2 domain) + running max
        const float2* kp = (const float2*)(sm + AKPOS + st * 512);
        float mn0 = m_0, mn1 = m_1;
        #pragma unroll
        for (int a = 0; a < 8; a++) {
            int c0 = a * 8 + tig * 2;
            float2 ka = kp[c0];
            float2 kb = kp[c0 + 1];
            float dxa0 = qp0.x - ka.x, dya0 = qp0.y - ka.y;
            float dxb0 = qp0.x - kb.x, dyb0 = qp0.y - kb.y;
            float dxa1 = qp1.x - ka.x, dya1 = qp1.y - ka.y;
            float dxb1 = qp1.x - kb.x, dyb1 = qp1.y - kb.y;
            sacc[a][0] = sacc[a][0] * SC_QK - (dxa0*dxa0 + dya0*dya0) * SC_BIAS;
            sacc[a][1] = sacc[a][1] * SC_QK - (dxb0*dxb0 + dyb0*dyb0) * SC_BIAS;
            sacc[a][2] = sacc[a][2] * SC_QK - (dxa1*dxa1 + dya1*dya1) * SC_BIAS;
            sacc[a][3] = sacc[a][3] * SC_QK - (dxb1*dxb1 + dyb1*dyb1) * SC_BIAS;
            mn0 = fmaxf(mn0, fmaxf(sacc[a][0], sacc[a][1]));
            mn1 = fmaxf(mn1, fmaxf(sacc[a][2], sacc[a][3]));
        }
        mn0 = fmaxf(mn0, __shfl_xor_sync(0xffffffffu, mn0, 1));
        mn0 = fmaxf(mn0, __shfl_xor_sync(0xffffffffu, mn0, 2));
        mn1 = fmaxf(mn1, __shfl_xor_sync(0xffffffffu, mn1, 1));
        mn1 = fmaxf(mn1, __shfl_xor_sync(0xffffffffu, mn1, 2));

        // ---- warp-vote rescale skip (corr==1 when max unchanged)
        bool changed = (mn0 > m_0) || (mn1 > m_1);
        if (__any_sync(0xffffffffu, changed)) {
            float corr0 = exp2f(m_0 - mn0);
            float corr1 = exp2f(m_1 - mn1);
            m_0 = mn0; m_1 = mn1;
            l_0 *= corr0; l_1 *= corr1;
            #pragma unroll
            for (int a = 0; a < 18; a++) {
                oacc[a][0] *= corr0; oacc[a][1] *= corr0;
                oacc[a][2] *= corr1; oacc[a][3] *= corr1;
            }
        }

        #pragma unroll
        for (int a = 0; a < 8; a++) {
            float p0 = exp2f(sacc[a][0] - m_0);
            float p1 = exp2f(sacc[a][1] - m_0);
            float p2 = exp2f(sacc[a][2] - m_1);
            float p3 = exp2f(sacc[a][3] - m_1);
            l_0 += p0 + p1; l_1 += p2 + p3;
            sacc[a][0] = p0; sacc[a][1] = p1; sacc[a][2] = p2; sacc[a][3] = p3;
        }

        #pragma unroll
        for (int kc4 = 0; kc4 < 4; kc4++) {
            uint32_t pa[4];
            pa[0] = pack_h2(sacc[2*kc4][0],   sacc[2*kc4][1]);
            pa[1] = pack_h2(sacc[2*kc4][2],   sacc[2*kc4][3]);
            pa[2] = pack_h2(sacc[2*kc4+1][0], sacc[2*kc4+1][1]);
            pa[3] = pack_h2(sacc[2*kc4+1][2], sacc[2*kc4+1][3]);
            uint32_t vf[2][4];
            ldm4t(vhb + kc4 * (16 * APITCH), vf[0]);
            #pragma unroll
            for (int dp = 0; dp < 9; dp++) {
                const int cur = dp & 1, nxt = cur ^ 1;
                if (dp < 8)
                    ldm4t(vhb + kc4 * (16 * APITCH) + (dp + 1) * 32, vf[nxt]);
                mma_f16(oacc[2*dp],   pa, vf[cur][0], vf[cur][1]);
                mma_f16(oacc[2*dp+1], pa, vf[cur][2], vf[cur][3]);
            }
        }
    }

    l_0 += __shfl_xor_sync(0xffffffffu, l_0, 1);
    l_0 += __shfl_xor_sync(0xffffffffu, l_0, 2);
    l_1 += __shfl_xor_sync(0xffffffffu, l_1, 1);
    l_1 += __shfl_xor_sync(0xffffffffu, l_1, 2);
    float inv0 = 1.f / l_0, inv1 = 1.f / l_1;

    size_t row0 = (size_t)t * M_TRK + m0 + w * 16 + gid;
    #pragma unroll
    for (int a = 0; a < 18; a++) {
        int col = h * DH + a * 8 + tig * 2;
        *(__half2*)(Sh + row0 * DM + col) =
            __floats2half2_rn(oacc[a][0] * inv0, oacc[a][1] * inv0);
        *(__half2*)(Sh + (row0 + 8) * DM + col) =
            __floats2half2_rn(oacc[a][2] * inv1, oacc[a][3] * inv1);
    }
}

// ---------------- launch ----------------
extern "C" void kernel_launch(void* const* d_in, const int* in_sizes, int n_in,
                              void* d_out, int out_size)
{
    const float* features    = (const float*)d_in[0];
    const float* tracks      = (const float*)d_in[1];
    const float* track_toks  = (const float*)d_in[2];
    const float* fpos        = (const float*)d_in[3];
    const float* W_q         = (const float*)d_in[4];
    const float* W_k         = (const float*)d_in[5];
    const float* q_norm_w    = (const float*)d_in[6];
    const float* k_norm_w    = (const float*)d_in[7];
    const float* out_proj_w  = (const float*)d_in[8];
    float* out = (float*)d_out;

    __half *gQg, *gKg, *gTTh, *gFh, *gWq, *gWk, *gWo, *gQh, *gKh, *gSh;
    cudaGetSymbolAddress((void**)&gQg, g_Qg);
    cudaGetSymbolAddress((void**)&gKg, g_Kg);
    cudaGetSymbolAddress((void**)&gTTh, g_TTh);
    cudaGetSymbolAddress((void**)&gFh, g_Fh);
    cudaGetSymbolAddress((void**)&gWq, g_Wq);
    cudaGetSymbolAddress((void**)&gWk, g_Wk);
    cudaGetSymbolAddress((void**)&gWo, g_Wo);
    cudaGetSymbolAddress((void**)&gQh, g_Qh);
    cudaGetSymbolAddress((void**)&gKh, g_Kh);
    cudaGetSymbolAddress((void**)&gSh, g_Sh);

    cudaFuncSetAttribute(gemm_qk_kernel,
                         cudaFuncAttributeMaxDynamicSharedMemorySize, GEMM_SMEM);
    cudaFuncSetAttribute(gemm_out_kernel,
                         cudaFuncAttributeMaxDynamicSharedMemorySize, GEMM_SMEM);
    cudaFuncSetAttribute(attn_mma_kernel,
                         cudaFuncAttributeMaxDynamicSharedMemorySize, ATTN_SMEM);

    // ---- fused converts + all weight tables + RoPE table ----
    f32_to_f16_dual<<<4096, 256>>>(track_toks, gTTh, (long)MQ * DM / 4,
                                   features, gFh, (long)MK * DM / 4);
    {
        dim3 g(DM / 32, DM / 32, 3);
        wt_f16_tri<<<g, 256>>>(W_q, gWq, W_k, gWk, out_proj_w, gWo);
    }
    rope_tab_kernel<<<HW_DIM, 256>>>(fpos);

    // ---- merged Q + K GEMM ----
    {
        dim3 g(DM / 128, MQB + MKB);
        gemm_qk_kernel<<<g, 128, GEMM_SMEM>>>(gTTh, gWq, gQg, gFh, gWk, gKg);
    }

    // ---- merged register-resident LN(Q) + RoPE+LN(K) ----
    ln_all_kernel<<<MQ + MK, 192>>>(gQg, q_norm_w, gQh, gKg, k_norm_w, gKh);

    // ---- fused tensor-core attention (V = features fp16) ----
    {
        dim3 g(M_TRK / 128, NH, T_DIM);
        attn_mma_kernel<<<g, 256, ATTN_SMEM>>>(gQh, gKh, gFh, tracks, fpos, gSh);
    }

    // ---- out = sampled @ out_proj_w (fp32 out) ----
    {
        dim3 g(DM / 128, MQB);
        gemm_out_kernel<<<g, 128, GEMM_SMEM>>>(gSh, gWo, out, MQ);
    }
}

// round 16
// speedup vs baseline: 1.1352x; 1.0039x over previous
#include <cuda_runtime.h>
#include <cuda_fp16.h>
#include <math.h>
#include <stdint.h>

// ---------------- problem constants ----------------
#define T_DIM   64
#define HW_DIM  729
#define M_TRK   512
#define DM      1152
#define NH      8
#define DH      144
#define MQ      (T_DIM * M_TRK)    // 32768
#define MK      (T_DIM * HW_DIM)   // 46656
#define MQB     (MQ / 128)         // 256
#define MKB     ((MK + 127) / 128) // 365

// ---------------- device scratch ----------------
__device__ __half g_Qg[(size_t)MQ * DM];
__device__ __half g_Kg[(size_t)MK * DM];
__device__ __half g_TTh[(size_t)MQ * DM];
__device__ __half g_Fh[(size_t)MK * DM];
__device__ __half g_Wq[(size_t)DM * DM];
__device__ __half g_Wk[(size_t)DM * DM];
__device__ __half g_Wo[(size_t)DM * DM];
__device__ __half g_Qh[(size_t)MQ * DM];
__device__ __half g_Kh[(size_t)MK * DM];
__device__ __half g_Sh[(size_t)MQ * DM];
__device__ float2 g_rtab[(size_t)HW_DIM * 576];

__device__ __forceinline__ uint32_t smem_u32(const void* p) {
    uint32_t a;
    asm("{ .reg .u64 t; cvta.to.shared.u64 t, %1; cvt.u32.u64 %0, t; }" : "=r"(a) : "l"(p));
    return a;
}
__device__ __forceinline__ void cp16(uint32_t dst, const void* src) {
    asm volatile("cp.async.cg.shared.global [%0], [%1], 16;" :: "r"(dst), "l"(src));
}
__device__ __forceinline__ void ldm4(uint32_t addr, uint32_t* r) {
    asm volatile("ldmatrix.sync.aligned.m8n8.x4.shared.b16 {%0,%1,%2,%3}, [%4];"
                 : "=r"(r[0]), "=r"(r[1]), "=r"(r[2]), "=r"(r[3])
                 : "r"(addr) : "memory");
}
__device__ __forceinline__ void ldm4t(uint32_t addr, uint32_t* r) {
    asm volatile("ldmatrix.sync.aligned.m8n8.x4.trans.shared.b16 {%0,%1,%2,%3}, [%4];"
                 : "=r"(r[0]), "=r"(r[1]), "=r"(r[2]), "=r"(r[3])
                 : "r"(addr) : "memory");
}
__device__ __forceinline__ void mma_f16(float* d, const uint32_t* a,
                                        uint32_t b0, uint32_t b1) {
    asm volatile(
        "mma.sync.aligned.m16n8k16.row.col.f32.f16.f16.f32 "
        "{%0,%1,%2,%3}, {%4,%5,%6,%7}, {%8,%9}, {%0,%1,%2,%3};"
        : "+f"(d[0]), "+f"(d[1]), "+f"(d[2]), "+f"(d[3])
        : "r"(a[0]), "r"(a[1]), "r"(a[2]), "r"(a[3]), "r"(b0), "r"(b1));
}
__device__ __forceinline__ uint32_t pack_h2(float a, float b) {
    __half2 h = __floats2half2_rn(a, b);
    return *(uint32_t*)&h;
}

// ============ merged preprocessing: converts + weight transposes + rope ======
// block ranges: [0,4096) grid-stride converts; [4096,7984) weight tiles;
// [7984,8713) rope table rows.
#define PREP_CONV 4096
#define PREP_WT   (PREP_CONV + 3 * 36 * 36)   // 7984
#define PREP_TOT  (PREP_WT + HW_DIM)          // 8713

__global__ __launch_bounds__(256)
void prep_kernel(const float* __restrict__ tt, __half* __restrict__ TTh,
                 const float* __restrict__ feat, __half* __restrict__ Fh,
                 const float* __restrict__ Wq, __half* __restrict__ Hq,
                 const float* __restrict__ Wk, __half* __restrict__ Hk,
                 const float* __restrict__ Wo, __half* __restrict__ Ho,
                 const float* __restrict__ fpos)
{
    __shared__ float tile[32][33];
    const int b = blockIdx.x;

    if (b < PREP_CONV) {
        // grid-stride fp32 -> fp16 over track_tokens then features
        const long n0 = (long)MQ * DM / 4;
        const long tot = n0 + (long)MK * DM / 4;
        long i = (long)b * 256 + threadIdx.x;
        const long stride = (long)PREP_CONV * 256;
        for (; i < tot; i += stride) {
            const float* X; __half* O; long j;
            if (i < n0) { X = tt; O = TTh; j = i; }
            else        { X = feat; O = Fh; j = i - n0; }
            float4 v = ((const float4*)X)[j];
            ((__half2*)O)[2*j]   = __floats2half2_rn(v.x, v.y);
            ((__half2*)O)[2*j+1] = __floats2half2_rn(v.z, v.w);
        }
    } else if (b < PREP_WT) {
        // weight fp16 + transpose: W[K,N] -> Ht[N,K]
        int idx = b - PREP_CONV;
        int z = idx / 1296, rem = idx % 1296;
        const float* W = (z == 0) ? Wq : (z == 1) ? Wk : Wo;
        __half* Ht     = (z == 0) ? Hq : (z == 1) ? Hk : Ho;
        int nb = (rem % 36) * 32, kb = (rem / 36) * 32;
        int tx = threadIdx.x & 31, ty = threadIdx.x >> 5;
        #pragma unroll
        for (int r = ty; r < 32; r += 8)
            tile[r][tx] = W[(size_t)(kb + r) * DM + nb + tx];
        __syncthreads();
        #pragma unroll
        for (int r = ty; r < 32; r += 8)
            Ht[(size_t)(nb + r) * DM + kb + tx] = __float2half_rn(tile[tx][r]);
    } else {
        // RoPE cos/sin table for one position
        const int n = b - PREP_WT;
        const float px = fpos[2 * n];
        const float py = fpos[2 * n + 1];
        const float TS = -9.210340371976184f / 288.0f;
        for (int p = threadIdx.x; p < 576; p += 256) {
            int q = (p < 288) ? p : (p - 288);
            float theta = expf((float)q * TS);
            float ang = ((p < 288) ? px : py) * theta;
            float c, s;
            sincosf(ang, &s, &c);
            g_rtab[(size_t)n * 576 + p] = make_float2(c, s);
        }
    }
}

// =================== GEMM core (R13: BK=64, GNST=3, XOR swizzle) =============
#define GTB 16384
#define GSTG (2 * GTB)
#define GNST 3
#define GEMM_SMEM (GNST * GSTG)       // 98304
#define KC2 18

template <typename TO>
__device__ __forceinline__
void gemm_body(const __half* __restrict__ A, const __half* __restrict__ BhT,
               TO* __restrict__ C, int M, int m0, int n0, char* dsm)
{
    const int tid  = threadIdx.x;
    const int lane = tid & 31;
    const int wid  = tid >> 5;
    const int wm   = wid & 1;
    const int wn   = wid >> 1;

    uint32_t sb = smem_u32(dsm);
    const char* srcbase[2] = { (const char*)A, (const char*)BhT };

    float acc[4][8][4];
    #pragma unroll
    for (int i = 0; i < 4; i++)
        #pragma unroll
        for (int j = 0; j < 8; j++)
            #pragma unroll
            for (int q = 0; q < 4; q++) acc[i][j][q] = 0.f;

    auto load_stage = [&](int stage, int chunk) {
        uint32_t stb = sb + (uint32_t)stage * (uint32_t)GSTG;
        #pragma unroll
        for (int it = 0; it < 16; it++) {
            int flat = tid + it * 128;
            int t2 = flat >> 10;
            int r  = (flat >> 3) & 127;
            int c4 = flat & 7;
            int grow;
            if (t2 == 0) { grow = m0 + r; if (grow > M - 1) grow = M - 1; }
            else         { grow = n0 + r; }
            const char* src = srcbase[t2] + (size_t)grow * (DM * 2)
                              + (size_t)chunk * 128 + c4 * 16;
            uint32_t dst = stb + (uint32_t)t2 * (uint32_t)GTB
                           + (uint32_t)r * 128u + (uint32_t)((c4 ^ (r & 7)) << 4);
            cp16(dst, src);
        }
        asm volatile("cp.async.commit_group;" ::: "memory");
    };

    load_stage(0, 0);
    load_stage(1, 1);

    uint32_t xoff[4];
    #pragma unroll
    for (int kc = 0; kc < 4; kc++)
        xoff[kc] = (uint32_t)(((2 * kc + (lane >> 4)) ^ (lane & 7)) << 4);
    uint32_t aRow[4], bRow[4];
    #pragma unroll
    for (int i = 0; i < 4; i++) {
        aRow[i] = (uint32_t)(wm * 64 + i * 16 + (lane & 15)) * 128u;
        bRow[i] = (uint32_t)(wn * 64 + i * 16 + (lane & 15)) * 128u;
    }

    uint32_t ah[2][4][4], bh[2][4][4];

    for (int c = 0; c < KC2; c++) {
        const int s = c % GNST;
        if (c < KC2 - 1) asm volatile("cp.async.wait_group 1;" ::: "memory");
        else             asm volatile("cp.async.wait_group 0;" ::: "memory");
        __syncthreads();

        if (c + 2 < KC2) load_stage((c + 2) % GNST, c + 2);

        uint32_t stb = sb + (uint32_t)s * (uint32_t)GSTG;

        #pragma unroll
        for (int a = 0; a < 4; a++) ldm4(stb + aRow[a] + xoff[0], ah[0][a]);
        #pragma unroll
        for (int b = 0; b < 4; b++) ldm4(stb + GTB + bRow[b] + xoff[0], bh[0][b]);

        #pragma unroll
        for (int kc = 0; kc < 4; kc++) {
            const int cur = kc & 1, nxt = cur ^ 1;
            if (kc < 3) {
                #pragma unroll
                for (int a = 0; a < 4; a++) ldm4(stb + aRow[a] + xoff[kc+1], ah[nxt][a]);
                #pragma unroll
                for (int b = 0; b < 4; b++) ldm4(stb + GTB + bRow[b] + xoff[kc+1], bh[nxt][b]);
            }
            #pragma unroll
            for (int am = 0; am < 4; am++) {
                #pragma unroll
                for (int bt = 0; bt < 4; bt++) {
                    mma_f16(acc[am][2*bt],   ah[cur][am], bh[cur][bt][0], bh[cur][bt][2]);
                    mma_f16(acc[am][2*bt+1], ah[cur][am], bh[cur][bt][1], bh[cur][bt][3]);
                }
            }
        }
    }

    #pragma unroll
    for (int am = 0; am < 4; am++) {
        int m = m0 + wm * 64 + am * 16 + (lane >> 2);
        #pragma unroll
        for (int bt = 0; bt < 8; bt++) {
            int n = n0 + wn * 64 + bt * 8 + (lane & 3) * 2;
            if (sizeof(TO) == 4) {
                if (m < M)
                    *(float2*)((float*)C + (size_t)m * DM + n) =
                        make_float2(acc[am][bt][0], acc[am][bt][1]);
                if (m + 8 < M)
                    *(float2*)((float*)C + (size_t)(m + 8) * DM + n) =
                        make_float2(acc[am][bt][2], acc[am][bt][3]);
            } else {
                if (m < M)
                    *(__half2*)((__half*)C + (size_t)m * DM + n) =
                        __floats2half2_rn(acc[am][bt][0], acc[am][bt][1]);
                if (m + 8 < M)
                    *(__half2*)((__half*)C + (size_t)(m + 8) * DM + n) =
                        __floats2half2_rn(acc[am][bt][2], acc[am][bt][3]);
            }
        }
    }
}

__global__ __launch_bounds__(128)
void gemm_qk_kernel(const __half* __restrict__ Aq, const __half* __restrict__ Bq,
                    __half* __restrict__ Cq,
                    const __half* __restrict__ Ak, const __half* __restrict__ Bk,
                    __half* __restrict__ Ck)
{
    extern __shared__ char dsm[];
    const int n0 = blockIdx.x * 128;
    if (blockIdx.y < MQB)
        gemm_body<__half>(Aq, Bq, Cq, MQ, blockIdx.y * 128, n0, dsm);
    else
        gemm_body<__half>(Ak, Bk, Ck, MK, (blockIdx.y - MQB) * 128, n0, dsm);
}

__global__ __launch_bounds__(128)
void gemm_out_kernel(const __half* __restrict__ A, const __half* __restrict__ B,
                     float* __restrict__ C, int M)
{
    extern __shared__ char dsm[];
    gemm_body<float>(A, B, C, M, blockIdx.y * 128, blockIdx.x * 128, dsm);
}

// ---------------- register-resident merged LN(Q) + RoPE+LN(K) ----------------
__global__ __launch_bounds__(192)
void ln_all_kernel(const __half* __restrict__ Qg, const float* __restrict__ qw,
                   __half* __restrict__ Qo,
                   const __half* __restrict__ Kg, const float* __restrict__ kw,
                   __half* __restrict__ Ko)
{
    __shared__ float red[14];
    const int b = blockIdx.x;
    const bool isQ = (b < MQ);
    const int row = isQ ? b : (b - MQ);
    const __half2* x2 = (const __half2*)((isQ ? Qg : Kg) + (size_t)row * DM);
    const float2* w2 = (const float2*)(isQ ? qw : kw);
    __half2* o2 = (__half2*)((isQ ? Qo : Ko) + (size_t)row * DM);
    const int tid = threadIdx.x;

    float vx[3][2];
    if (isQ) {
        #pragma unroll
        for (int r = 0; r < 3; r++) {
            __half2 v = x2[tid + r * 192];
            vx[r][0] = __low2float(v);
            vx[r][1] = __high2float(v);
        }
    } else {
        const float2* rt = g_rtab + (size_t)(row % HW_DIM) * 576;
        #pragma unroll
        for (int r = 0; r < 3; r++) {
            int j = tid + r * 192;
            __half2 v = x2[j];
            float2 cs = rt[j];
            float a = __low2float(v), bb = __high2float(v);
            vx[r][0] = a * cs.x - bb * cs.y;
            vx[r][1] = a * cs.y + bb * cs.x;
        }
    }
    float s = 0.f, ss = 0.f;
    #pragma unroll
    for (int r = 0; r < 3; r++) {
        s  += vx[r][0] + vx[r][1];
        ss += vx[r][0] * vx[r][0] + vx[r][1] * vx[r][1];
    }
    #pragma unroll
    for (int o = 16; o; o >>= 1) {
        s  += __shfl_down_sync(0xffffffffu, s, o);
        ss += __shfl_down_sync(0xffffffffu, ss, o);
    }
    int wid = tid >> 5, lane = tid & 31;
    if (lane == 0) { red[wid] = s; red[6 + wid] = ss; }
    __syncthreads();
    if (tid == 0) {
        float S = 0.f, SS = 0.f;
        #pragma unroll
        for (int i = 0; i < 6; i++) { S += red[i]; SS += red[6 + i]; }
        red[12] = S; red[13] = SS;
    }
    __syncthreads();
    float mu  = red[12] * (1.f / DM);
    float var = red[13] * (1.f / DM) - mu * mu;
    float inv = rsqrtf(var + 1e-6f);
    #pragma unroll
    for (int r = 0; r < 3; r++) {
        int j = tid + r * 192;
        float2 w = w2[j];
        o2[j] = __floats2half2_rn((vx[r][0] - mu) * inv * w.x,
                                  (vx[r][1] - mu) * inv * w.y);
    }
}

// ---------------- tensor-core fused attention (log2 softmax, vote rescale) ---
#define APITCH 304
#define ATSZ   (64 * APITCH)
#define ASTG   (2 * ATSZ)
#define ANST   3
#define AKPOS  (ANST * ASTG)
#define ATTN_SMEM (AKPOS + ANST * 512)

#define SC_QK   0.1202245867f   // log2(e) / 12
#define SC_BIAS 0.1803368801f   // log2(e) / 8

__global__ __launch_bounds__(256, 1)
void attn_mma_kernel(const __half* __restrict__ Qh, const __half* __restrict__ Kh,
                     const __half* __restrict__ Vh,
                     const float* __restrict__ tracks, const float* __restrict__ fpos,
                     __half* __restrict__ Sh)
{
    extern __shared__ char sm[];
    uint32_t sb = smem_u32(sm);
    const int tid  = threadIdx.x;
    const int lane = tid & 31;
    const int w    = tid >> 5;
    const int gid  = lane >> 2;
    const int tig  = lane & 3;
    const int m0   = blockIdx.x * 128;
    const int h    = blockIdx.y;
    const int t    = blockIdx.z;

    const char* qbase  = (const char*)(Qh + ((size_t)t * M_TRK + m0) * DM + h * DH);
    const char* khbase = (const char*)(Kh + (size_t)t * HW_DIM * DM + h * DH);
    const char* vbase  = (const char*)(Vh + (size_t)t * HW_DIM * DM + h * DH);

    float2 qp0 = *(const float2*)(tracks + ((size_t)t * M_TRK + m0 + w * 16 + gid) * 2);
    float2 qp1 = *(const float2*)(tracks + ((size_t)t * M_TRK + m0 + w * 16 + gid + 8) * 2);

    #pragma unroll
    for (int i = 0; i < 9; i++) {
        int c = tid + i * 256;
        int row = c / 18, ch = c % 18;
        cp16(sb + row * APITCH + ch * 16, qbase + (size_t)row * (DM * 2) + ch * 16);
    }
    asm volatile("cp.async.commit_group;" ::: "memory");
    asm volatile("cp.async.wait_group 0;" ::: "memory");
    __syncthreads();

    uint32_t qf[9][4];
    {
        uint32_t qa = sb + (uint32_t)(w * 16 + (lane & 15)) * APITCH + (uint32_t)(lane >> 4) * 16u;
        #pragma unroll
        for (int kc = 0; kc < 9; kc++) ldm4(qa + kc * 32, qf[kc]);
    }
    __syncthreads();

    auto load_tile = [&](int st, int kt) {
        int k0 = kt * 64;
        uint32_t stb = sb + (uint32_t)st * (uint32_t)ASTG;
        #pragma unroll
        for (int i = 0; i < 9; i++) {
            int c = tid + i * 256;
            int buf = c / 1152, rem = c % 1152;
            int row = rem / 18, ch = rem % 18;
            int krow = k0 + row; if (krow > HW_DIM - 1) krow = HW_DIM - 1;
            const char* src = (buf == 0) ? khbase : vbase;
            cp16(stb + (uint32_t)buf * (uint32_t)ATSZ + (uint32_t)row * APITCH + (uint32_t)ch * 16u,
                 src + (size_t)krow * (DM * 2) + ch * 16);
        }
        asm volatile("cp.async.commit_group;" ::: "memory");
        if (tid < 64) {
            int kr = k0 + tid;
            float2 v = (kr < HW_DIM) ? *(const float2*)(fpos + (size_t)kr * 2)
                                     : make_float2(1e5f, 1e5f);
            *(float2*)(sm + AKPOS + st * 512 + tid * 8) = v;
        }
    };

    load_tile(0, 0);
    load_tile(1, 1);

    float m_0 = -1e30f, m_1 = -1e30f, l_0 = 0.f, l_1 = 0.f;
    float oacc[18][4];
    #pragma unroll
    for (int a = 0; a < 18; a++)
        #pragma unroll
        for (int q = 0; q < 4; q++) oacc[a][q] = 0.f;

    const int NT = (HW_DIM + 63) / 64;   // 12
    for (int kt = 0; kt < NT; kt++) {
        const int st = kt % ANST;
        if (kt < NT - 1) asm volatile("cp.async.wait_group 1;" ::: "memory");
        else             asm volatile("cp.async.wait_group 0;" ::: "memory");
        __syncthreads();

        if (kt + 2 < NT) load_tile((kt + 2) % ANST, kt + 2);

        uint32_t stb = sb + (uint32_t)st * (uint32_t)ASTG;
        uint32_t lrow = (uint32_t)(lane & 15) * APITCH + (uint32_t)(lane >> 4) * 16u;
        uint32_t khb = stb + lrow;
        uint32_t vhb = stb + ATSZ + lrow;

        float sacc[8][4];
        #pragma unroll
        for (int a = 0; a < 8; a++)
            #pragma unroll
            for (int q = 0; q < 4; q++) sacc[a][q] = 0.f;

        uint32_t bhf[2][4][4];
        #pragma unroll
        for (int g = 0; g < 4; g++) ldm4(khb + g * (16 * APITCH), bhf[0][g]);
        #pragma unroll
        for (int kc = 0; kc < 9; kc++) {
            const int cur = kc & 1, nxt = cur ^ 1;
            if (kc < 8) {
                #pragma unroll
                for (int g = 0; g < 4; g++)
                    ldm4(khb + g * (16 * APITCH) + (kc + 1) * 32, bhf[nxt][g]);
            }
            #pragma unroll
            for (int g = 0; g < 4; g++) {
                mma_f16(sacc[2*g],   qf[kc], bhf[cur][g][0], bhf[cur][g][2]);
                mma_f16(sacc[2*g+1], qf[kc], bhf[cur][g][1], bhf[cur][g][3]);
            }
        }

        const float2* kp = (const float2*)(sm + AKPOS + st * 512);
        float mn0 = m_0, mn1 = m_1;
        #pragma unroll
        for (int a = 0; a < 8; a++) {
            int c0 = a * 8 + tig * 2;
            float2 ka = kp[c0];
            float2 kb = kp[c0 + 1];
            float dxa0 = qp0.x - ka.x, dya0 = qp0.y - ka.y;
            float dxb0 = qp0.x - kb.x, dyb0 = qp0.y - kb.y;
            float dxa1 = qp1.x - ka.x, dya1 = qp1.y - ka.y;
            float dxb1 = qp1.x - kb.x, dyb1 = qp1.y - kb.y;
            sacc[a][0] = sacc[a][0] * SC_QK - (dxa0*dxa0 + dya0*dya0) * SC_BIAS;
            sacc[a][1] = sacc[a][1] * SC_QK - (dxb0*dxb0 + dyb0*dyb0) * SC_BIAS;
            sacc[a][2] = sacc[a][2] * SC_QK - (dxa1*dxa1 + dya1*dya1) * SC_BIAS;
            sacc[a][3] = sacc[a][3] * SC_QK - (dxb1*dxb1 + dyb1*dyb1) * SC_BIAS;
            mn0 = fmaxf(mn0, fmaxf(sacc[a][0], sacc[a][1]));
            mn1 = fmaxf(mn1, fmaxf(sacc[a][2], sacc[a][3]));
        }
        mn0 = fmaxf(mn0, __shfl_xor_sync(0xffffffffu, mn0, 1));
        mn0 = fmaxf(mn0, __shfl_xor_sync(0xffffffffu, mn0, 2));
        mn1 = fmaxf(mn1, __shfl_xor_sync(0xffffffffu, mn1, 1));
        mn1 = fmaxf(mn1, __shfl_xor_sync(0xffffffffu, mn1, 2));

        bool changed = (mn0 > m_0) || (mn1 > m_1);
        if (__any_sync(0xffffffffu, changed)) {
            float corr0 = exp2f(m_0 - mn0);
            float corr1 = exp2f(m_1 - mn1);
            m_0 = mn0; m_1 = mn1;
            l_0 *= corr0; l_1 *= corr1;
            #pragma unroll
            for (int a = 0; a < 18; a++) {
                oacc[a][0] *= corr0; oacc[a][1] *= corr0;
                oacc[a][2] *= corr1; oacc[a][3] *= corr1;
            }
        }

        #pragma unroll
        for (int a = 0; a < 8; a++) {
            float p0 = exp2f(sacc[a][0] - m_0);
            float p1 = exp2f(sacc[a][1] - m_0);
            float p2 = exp2f(sacc[a][2] - m_1);
            float p3 = exp2f(sacc[a][3] - m_1);
            l_0 += p0 + p1; l_1 += p2 + p3;
            sacc[a][0] = p0; sacc[a][1] = p1; sacc[a][2] = p2; sacc[a][3] = p3;
        }

        #pragma unroll
        for (int kc4 = 0; kc4 < 4; kc4++) {
            uint32_t pa[4];
            pa[0] = pack_h2(sacc[2*kc4][0],   sacc[2*kc4][1]);
            pa[1] = pack_h2(sacc[2*kc4][2],   sacc[2*kc4][3]);
            pa[2] = pack_h2(sacc[2*kc4+1][0], sacc[2*kc4+1][1]);
            pa[3] = pack_h2(sacc[2*kc4+1][2], sacc[2*kc4+1][3]);
            uint32_t vf[2][4];
            ldm4t(vhb + kc4 * (16 * APITCH), vf[0]);
            #pragma unroll
            for (int dp = 0; dp < 9; dp++) {
                const int cur = dp & 1, nxt = cur ^ 1;
                if (dp < 8)
                    ldm4t(vhb + kc4 * (16 * APITCH) + (dp + 1) * 32, vf[nxt]);
                mma_f16(oacc[2*dp],   pa, vf[cur][0], vf[cur][1]);
                mma_f16(oacc[2*dp+1], pa, vf[cur][2], vf[cur][3]);
            }
        }
    }

    l_0 += __shfl_xor_sync(0xffffffffu, l_0, 1);
    l_0 += __shfl_xor_sync(0xffffffffu, l_0, 2);
    l_1 += __shfl_xor_sync(0xffffffffu, l_1, 1);
    l_1 += __shfl_xor_sync(0xffffffffu, l_1, 2);
    float inv0 = 1.f / l_0, inv1 = 1.f / l_1;

    size_t row0 = (size_t)t * M_TRK + m0 + w * 16 + gid;
    #pragma unroll
    for (int a = 0; a < 18; a++) {
        int col = h * DH + a * 8 + tig * 2;
        *(__half2*)(Sh + row0 * DM + col) =
            __floats2half2_rn(oacc[a][0] * inv0, oacc[a][1] * inv0);
        *(__half2*)(Sh + (row0 + 8) * DM + col) =
            __floats2half2_rn(oacc[a][2] * inv1, oacc[a][3] * inv1);
    }
}

// ---------------- launch ----------------
extern "C" void kernel_launch(void* const* d_in, const int* in_sizes, int n_in,
                              void* d_out, int out_size)
{
    const float* features    = (const float*)d_in[0];
    const float* tracks      = (const float*)d_in[1];
    const float* track_toks  = (const float*)d_in[2];
    const float* fpos        = (const float*)d_in[3];
    const float* W_q         = (const float*)d_in[4];
    const float* W_k         = (const float*)d_in[5];
    const float* q_norm_w    = (const float*)d_in[6];
    const float* k_norm_w    = (const float*)d_in[7];
    const float* out_proj_w  = (const float*)d_in[8];
    float* out = (float*)d_out;

    __half *gQg, *gKg, *gTTh, *gFh, *gWq, *gWk, *gWo, *gQh, *gKh, *gSh;
    cudaGetSymbolAddress((void**)&gQg, g_Qg);
    cudaGetSymbolAddress((void**)&gKg, g_Kg);
    cudaGetSymbolAddress((void**)&gTTh, g_TTh);
    cudaGetSymbolAddress((void**)&gFh, g_Fh);
    cudaGetSymbolAddress((void**)&gWq, g_Wq);
    cudaGetSymbolAddress((void**)&gWk, g_Wk);
    cudaGetSymbolAddress((void**)&gWo, g_Wo);
    cudaGetSymbolAddress((void**)&gQh, g_Qh);
    cudaGetSymbolAddress((void**)&gKh, g_Kh);
    cudaGetSymbolAddress((void**)&gSh, g_Sh);

    cudaFuncSetAttribute(gemm_qk_kernel,
                         cudaFuncAttributeMaxDynamicSharedMemorySize, GEMM_SMEM);
    cudaFuncSetAttribute(gemm_out_kernel,
                         cudaFuncAttributeMaxDynamicSharedMemorySize, GEMM_SMEM);
    cudaFuncSetAttribute(attn_mma_kernel,
                         cudaFuncAttributeMaxDynamicSharedMemorySize, ATTN_SMEM);

    // ---- single merged preprocessing launch ----
    prep_kernel<<<PREP_TOT, 256>>>(track_toks, gTTh, features, gFh,
                                   W_q, gWq, W_k, gWk, out_proj_w, gWo, fpos);

    // ---- merged Q + K GEMM ----
    {
        dim3 g(DM / 128, MQB + MKB);
        gemm_qk_kernel<<<g, 128, GEMM_SMEM>>>(gTTh, gWq, gQg, gFh, gWk, gKg);
    }

    // ---- merged register-resident LN(Q) + RoPE+LN(K) ----
    ln_all_kernel<<<MQ + MK, 192>>>(gQg, q_norm_w, gQh, gKg, k_norm_w, gKh);

    // ---- fused tensor-core attention (V = features fp16) ----
    {
        dim3 g(M_TRK / 128, NH, T_DIM);
        attn_mma_kernel<<<g, 256, ATTN_SMEM>>>(gQh, gKh, gFh, tracks, fpos, gSh);
    }

    // ---- out = sampled @ out_proj_w (fp32 out) ----
    {
        dim3 g(DM / 128, MQB);
        gemm_out_kernel<<<g, 128, GEMM_SMEM>>>(gSh, gWo, out, MQ);
    }
}

// round 17
// speedup vs baseline: 1.1686x; 1.0294x over previous
#include <cuda_runtime.h>
#include <cuda_fp16.h>
#include <math.h>
#include <stdint.h>

// ---------------- problem constants ----------------
#define T_DIM   64
#define HW_DIM  729
#define M_TRK   512
#define DM      1152
#define NH      8
#define DH      144
#define MQ      (T_DIM * M_TRK)    // 32768
#define MK      (T_DIM * HW_DIM)   // 46656
#define MQB     (MQ / 128)         // 256
#define MKB     ((MK + 127) / 128) // 365

// ---------------- device scratch ----------------
__device__ __half g_Qg[(size_t)MQ * DM];
__device__ __half g_Kg[(size_t)MK * DM];
__device__ __half g_TTh[(size_t)MQ * DM];
__device__ __half g_Fh[(size_t)MK * DM];
__device__ __half g_Wq[(size_t)DM * DM];
__device__ __half g_Wk[(size_t)DM * DM];
__device__ __half g_Wo[(size_t)DM * DM];
__device__ __half g_Qh[(size_t)MQ * DM];
__device__ __half g_Kh[(size_t)MK * DM];
__device__ __half g_Sh[(size_t)MQ * DM];
__device__ float2 g_rtab[(size_t)HW_DIM * 576];

__device__ __forceinline__ uint32_t smem_u32(const void* p) {
    uint32_t a;
    asm("{ .reg .u64 t; cvta.to.shared.u64 t, %1; cvt.u32.u64 %0, t; }" : "=r"(a) : "l"(p));
    return a;
}
__device__ __forceinline__ void cp16(uint32_t dst, const void* src) {
    asm volatile("cp.async.cg.shared.global [%0], [%1], 16;" :: "r"(dst), "l"(src));
}
__device__ __forceinline__ void ldm4(uint32_t addr, uint32_t* r) {
    asm volatile("ldmatrix.sync.aligned.m8n8.x4.shared.b16 {%0,%1,%2,%3}, [%4];"
                 : "=r"(r[0]), "=r"(r[1]), "=r"(r[2]), "=r"(r[3])
                 : "r"(addr) : "memory");
}
__device__ __forceinline__ void ldm4t(uint32_t addr, uint32_t* r) {
    asm volatile("ldmatrix.sync.aligned.m8n8.x4.trans.shared.b16 {%0,%1,%2,%3}, [%4];"
                 : "=r"(r[0]), "=r"(r[1]), "=r"(r[2]), "=r"(r[3])
                 : "r"(addr) : "memory");
}
__device__ __forceinline__ void mma_f16(float* d, const uint32_t* a,
                                        uint32_t b0, uint32_t b1) {
    asm volatile(
        "mma.sync.aligned.m16n8k16.row.col.f32.f16.f16.f32 "
        "{%0,%1,%2,%3}, {%4,%5,%6,%7}, {%8,%9}, {%0,%1,%2,%3};"
        : "+f"(d[0]), "+f"(d[1]), "+f"(d[2]), "+f"(d[3])
        : "r"(a[0]), "r"(a[1]), "r"(a[2]), "r"(a[3]), "r"(b0), "r"(b1));
}
__device__ __forceinline__ uint32_t pack_h2(float a, float b) {
    __half2 h = __floats2half2_rn(a, b);
    return *(uint32_t*)&h;
}

// ============ merged preprocessing: converts + weight transposes + rope ======
#define PREP_CONV 4096
#define PREP_WT   (PREP_CONV + 3 * 36 * 36)   // 7984
#define PREP_TOT  (PREP_WT + HW_DIM)          // 8713

__global__ __launch_bounds__(256)
void prep_kernel(const float* __restrict__ tt, __half* __restrict__ TTh,
                 const float* __restrict__ feat, __half* __restrict__ Fh,
                 const float* __restrict__ Wq, __half* __restrict__ Hq,
                 const float* __restrict__ Wk, __half* __restrict__ Hk,
                 const float* __restrict__ Wo, __half* __restrict__ Ho,
                 const float* __restrict__ fpos)
{
    __shared__ float tile[32][33];
    const int b = blockIdx.x;

    if (b < PREP_CONV) {
        const long n0 = (long)MQ * DM / 4;
        const long tot = n0 + (long)MK * DM / 4;
        long i = (long)b * 256 + threadIdx.x;
        const long stride = (long)PREP_CONV * 256;
        for (; i < tot; i += stride) {
            const float* X; __half* O; long j;
            if (i < n0) { X = tt; O = TTh; j = i; }
            else        { X = feat; O = Fh; j = i - n0; }
            float4 v = ((const float4*)X)[j];
            ((__half2*)O)[2*j]   = __floats2half2_rn(v.x, v.y);
            ((__half2*)O)[2*j+1] = __floats2half2_rn(v.z, v.w);
        }
    } else if (b < PREP_WT) {
        int idx = b - PREP_CONV;
        int z = idx / 1296, rem = idx % 1296;
        const float* W = (z == 0) ? Wq : (z == 1) ? Wk : Wo;
        __half* Ht     = (z == 0) ? Hq : (z == 1) ? Hk : Ho;
        int nb = (rem % 36) * 32, kb = (rem / 36) * 32;
        int tx = threadIdx.x & 31, ty = threadIdx.x >> 5;
        #pragma unroll
        for (int r = ty; r < 32; r += 8)
            tile[r][tx] = W[(size_t)(kb + r) * DM + nb + tx];
        __syncthreads();
        #pragma unroll
        for (int r = ty; r < 32; r += 8)
            Ht[(size_t)(nb + r) * DM + kb + tx] = __float2half_rn(tile[tx][r]);
    } else {
        const int n = b - PREP_WT;
        const float px = fpos[2 * n];
        const float py = fpos[2 * n + 1];
        const float TS = -9.210340371976184f / 288.0f;
        for (int p = threadIdx.x; p < 576; p += 256) {
            int q = (p < 288) ? p : (p - 288);
            float theta = expf((float)q * TS);
            float ang = ((p < 288) ? px : py) * theta;
            float c, s;
            sincosf(ang, &s, &c);
            g_rtab[(size_t)n * 576 + p] = make_float2(c, s);
        }
    }
}

// =================== GEMM core (R13: BK=64, GNST=3, XOR swizzle) =============
#define GTB 16384
#define GSTG (2 * GTB)
#define GNST 3
#define GEMM_SMEM (GNST * GSTG)       // 98304
#define KC2 18

template <typename TO>
__device__ __forceinline__
void gemm_body(const __half* __restrict__ A, const __half* __restrict__ BhT,
               TO* __restrict__ C, int M, int m0, int n0, char* dsm)
{
    const int tid  = threadIdx.x;
    const int lane = tid & 31;
    const int wid  = tid >> 5;
    const int wm   = wid & 1;
    const int wn   = wid >> 1;

    uint32_t sb = smem_u32(dsm);
    const char* srcbase[2] = { (const char*)A, (const char*)BhT };

    float acc[4][8][4];
    #pragma unroll
    for (int i = 0; i < 4; i++)
        #pragma unroll
        for (int j = 0; j < 8; j++)
            #pragma unroll
            for (int q = 0; q < 4; q++) acc[i][j][q] = 0.f;

    auto load_stage = [&](int stage, int chunk) {
        uint32_t stb = sb + (uint32_t)stage * (uint32_t)GSTG;
        #pragma unroll
        for (int it = 0; it < 16; it++) {
            int flat = tid + it * 128;
            int t2 = flat >> 10;
            int r  = (flat >> 3) & 127;
            int c4 = flat & 7;
            int grow;
            if (t2 == 0) { grow = m0 + r; if (grow > M - 1) grow = M - 1; }
            else         { grow = n0 + r; }
            const char* src = srcbase[t2] + (size_t)grow * (DM * 2)
                              + (size_t)chunk * 128 + c4 * 16;
            uint32_t dst = stb + (uint32_t)t2 * (uint32_t)GTB
                           + (uint32_t)r * 128u + (uint32_t)((c4 ^ (r & 7)) << 4);
            cp16(dst, src);
        }
        asm volatile("cp.async.commit_group;" ::: "memory");
    };

    load_stage(0, 0);
    load_stage(1, 1);

    uint32_t xoff[4];
    #pragma unroll
    for (int kc = 0; kc < 4; kc++)
        xoff[kc] = (uint32_t)(((2 * kc + (lane >> 4)) ^ (lane & 7)) << 4);
    uint32_t aRow[4], bRow[4];
    #pragma unroll
    for (int i = 0; i < 4; i++) {
        aRow[i] = (uint32_t)(wm * 64 + i * 16 + (lane & 15)) * 128u;
        bRow[i] = (uint32_t)(wn * 64 + i * 16 + (lane & 15)) * 128u;
    }

    uint32_t ah[2][4][4], bh[2][4][4];

    for (int c = 0; c < KC2; c++) {
        const int s = c % GNST;
        if (c < KC2 - 1) asm volatile("cp.async.wait_group 1;" ::: "memory");
        else             asm volatile("cp.async.wait_group 0;" ::: "memory");
        __syncthreads();

        if (c + 2 < KC2) load_stage((c + 2) % GNST, c + 2);

        uint32_t stb = sb + (uint32_t)s * (uint32_t)GSTG;

        #pragma unroll
        for (int a = 0; a < 4; a++) ldm4(stb + aRow[a] + xoff[0], ah[0][a]);
        #pragma unroll
        for (int b = 0; b < 4; b++) ldm4(stb + GTB + bRow[b] + xoff[0], bh[0][b]);

        #pragma unroll
        for (int kc = 0; kc < 4; kc++) {
            const int cur = kc & 1, nxt = cur ^ 1;
            if (kc < 3) {
                #pragma unroll
                for (int a = 0; a < 4; a++) ldm4(stb + aRow[a] + xoff[kc+1], ah[nxt][a]);
                #pragma unroll
                for (int b = 0; b < 4; b++) ldm4(stb + GTB + bRow[b] + xoff[kc+1], bh[nxt][b]);
            }
            #pragma unroll
            for (int am = 0; am < 4; am++) {
                #pragma unroll
                for (int bt = 0; bt < 4; bt++) {
                    mma_f16(acc[am][2*bt],   ah[cur][am], bh[cur][bt][0], bh[cur][bt][2]);
                    mma_f16(acc[am][2*bt+1], ah[cur][am], bh[cur][bt][1], bh[cur][bt][3]);
                }
            }
        }
    }

    #pragma unroll
    for (int am = 0; am < 4; am++) {
        int m = m0 + wm * 64 + am * 16 + (lane >> 2);
        #pragma unroll
        for (int bt = 0; bt < 8; bt++) {
            int n = n0 + wn * 64 + bt * 8 + (lane & 3) * 2;
            if (sizeof(TO) == 4) {
                if (m < M)
                    *(float2*)((float*)C + (size_t)m * DM + n) =
                        make_float2(acc[am][bt][0], acc[am][bt][1]);
                if (m + 8 < M)
                    *(float2*)((float*)C + (size_t)(m + 8) * DM + n) =
                        make_float2(acc[am][bt][2], acc[am][bt][3]);
            } else {
                if (m < M)
                    *(__half2*)((__half*)C + (size_t)m * DM + n) =
                        __floats2half2_rn(acc[am][bt][0], acc[am][bt][1]);
                if (m + 8 < M)
                    *(__half2*)((__half*)C + (size_t)(m + 8) * DM + n) =
                        __floats2half2_rn(acc[am][bt][2], acc[am][bt][3]);
            }
        }
    }
}

__global__ __launch_bounds__(128)
void gemm_h_kernel(const __half* __restrict__ A, const __half* __restrict__ B,
                   __half* __restrict__ C, int M)
{
    extern __shared__ char dsm[];
    gemm_body<__half>(A, B, C, M, blockIdx.y * 128, blockIdx.x * 128, dsm);
}

__global__ __launch_bounds__(128)
void gemm_out_kernel(const __half* __restrict__ A, const __half* __restrict__ B,
                     float* __restrict__ C, int M)
{
    extern __shared__ char dsm[];
    gemm_body<float>(A, B, C, M, blockIdx.y * 128, blockIdx.x * 128, dsm);
}

// ---------------- register-resident LN kernels (Q plain, K rope) -------------
__device__ __forceinline__
void ln_row(const __half2* __restrict__ x2, const float2* __restrict__ w2,
            __half2* __restrict__ o2, const float2* __restrict__ rt, bool rope)
{
    __shared__ float red[14];
    const int tid = threadIdx.x;
    float vx[3][2];
    if (!rope) {
        #pragma unroll
        for (int r = 0; r < 3; r++) {
            __half2 v = x2[tid + r * 192];
            vx[r][0] = __low2float(v);
            vx[r][1] = __high2float(v);
        }
    } else {
        #pragma unroll
        for (int r = 0; r < 3; r++) {
            int j = tid + r * 192;
            __half2 v = x2[j];
            float2 cs = rt[j];
            float a = __low2float(v), bb = __high2float(v);
            vx[r][0] = a * cs.x - bb * cs.y;
            vx[r][1] = a * cs.y + bb * cs.x;
        }
    }
    float s = 0.f, ss = 0.f;
    #pragma unroll
    for (int r = 0; r < 3; r++) {
        s  += vx[r][0] + vx[r][1];
        ss += vx[r][0] * vx[r][0] + vx[r][1] * vx[r][1];
    }
    #pragma unroll
    for (int o = 16; o; o >>= 1) {
        s  += __shfl_down_sync(0xffffffffu, s, o);
        ss += __shfl_down_sync(0xffffffffu, ss, o);
    }
    int wid = tid >> 5, lane = tid & 31;
    if (lane == 0) { red[wid] = s; red[6 + wid] = ss; }
    __syncthreads();
    if (tid == 0) {
        float S = 0.f, SS = 0.f;
        #pragma unroll
        for (int i = 0; i < 6; i++) { S += red[i]; SS += red[6 + i]; }
        red[12] = S; red[13] = SS;
    }
    __syncthreads();
    float mu  = red[12] * (1.f / DM);
    float var = red[13] * (1.f / DM) - mu * mu;
    float inv = rsqrtf(var + 1e-6f);
    #pragma unroll
    for (int r = 0; r < 3; r++) {
        int j = tid + r * 192;
        float2 w = w2[j];
        o2[j] = __floats2half2_rn((vx[r][0] - mu) * inv * w.x,
                                  (vx[r][1] - mu) * inv * w.y);
    }
}

__global__ __launch_bounds__(192)
void ln_q_kernel(const __half* __restrict__ Qg, const float* __restrict__ qw,
                 __half* __restrict__ Qo)
{
    const int row = blockIdx.x;
    ln_row((const __half2*)(Qg + (size_t)row * DM), (const float2*)qw,
           (__half2*)(Qo + (size_t)row * DM), nullptr, false);
}

__global__ __launch_bounds__(192)
void ln_k_kernel(const __half* __restrict__ Kg, const float* __restrict__ kw,
                 __half* __restrict__ Ko)
{
    const int row = blockIdx.x;
    ln_row((const __half2*)(Kg + (size_t)row * DM), (const float2*)kw,
           (__half2*)(Ko + (size_t)row * DM),
           g_rtab + (size_t)(row % HW_DIM) * 576, true);
}

// ---------------- tensor-core fused attention (log2 softmax, vote rescale) ---
#define APITCH 304
#define ATSZ   (64 * APITCH)
#define ASTG   (2 * ATSZ)
#define ANST   3
#define AKPOS  (ANST * ASTG)
#define ATTN_SMEM (AKPOS + ANST * 512)

#define SC_QK   0.1202245867f   // log2(e) / 12
#define SC_BIAS 0.1803368801f   // log2(e) / 8

__global__ __launch_bounds__(256, 1)
void attn_mma_kernel(const __half* __restrict__ Qh, const __half* __restrict__ Kh,
                     const __half* __restrict__ Vh,
                     const float* __restrict__ tracks, const float* __restrict__ fpos,
                     __half* __restrict__ Sh)
{
    extern __shared__ char sm[];
    uint32_t sb = smem_u32(sm);
    const int tid  = threadIdx.x;
    const int lane = tid & 31;
    const int w    = tid >> 5;
    const int gid  = lane >> 2;
    const int tig  = lane & 3;
    const int m0   = blockIdx.x * 128;
    const int h    = blockIdx.y;
    const int t    = blockIdx.z;

    const char* qbase  = (const char*)(Qh + ((size_t)t * M_TRK + m0) * DM + h * DH);
    const char* khbase = (const char*)(Kh + (size_t)t * HW_DIM * DM + h * DH);
    const char* vbase  = (const char*)(Vh + (size_t)t * HW_DIM * DM + h * DH);

    float2 qp0 = *(const float2*)(tracks + ((size_t)t * M_TRK + m0 + w * 16 + gid) * 2);
    float2 qp1 = *(const float2*)(tracks + ((size_t)t * M_TRK + m0 + w * 16 + gid + 8) * 2);

    #pragma unroll
    for (int i = 0; i < 9; i++) {
        int c = tid + i * 256;
        int row = c / 18, ch = c % 18;
        cp16(sb + row * APITCH + ch * 16, qbase + (size_t)row * (DM * 2) + ch * 16);
    }
    asm volatile("cp.async.commit_group;" ::: "memory");
    asm volatile("cp.async.wait_group 0;" ::: "memory");
    __syncthreads();

    uint32_t qf[9][4];
    {
        uint32_t qa = sb + (uint32_t)(w * 16 + (lane & 15)) * APITCH + (uint32_t)(lane >> 4) * 16u;
        #pragma unroll
        for (int kc = 0; kc < 9; kc++) ldm4(qa + kc * 32, qf[kc]);
    }
    __syncthreads();

    auto load_tile = [&](int st, int kt) {
        int k0 = kt * 64;
        uint32_t stb = sb + (uint32_t)st * (uint32_t)ASTG;
        #pragma unroll
        for (int i = 0; i < 9; i++) {
            int c = tid + i * 256;
            int buf = c / 1152, rem = c % 1152;
            int row = rem / 18, ch = rem % 18;
            int krow = k0 + row; if (krow > HW_DIM - 1) krow = HW_DIM - 1;
            const char* src = (buf == 0) ? khbase : vbase;
            cp16(stb + (uint32_t)buf * (uint32_t)ATSZ + (uint32_t)row * APITCH + (uint32_t)ch * 16u,
                 src + (size_t)krow * (DM * 2) + ch * 16);
        }
        asm volatile("cp.async.commit_group;" ::: "memory");
        if (tid < 64) {
            int kr = k0 + tid;
            float2 v = (kr < HW_DIM) ? *(const float2*)(fpos + (size_t)kr * 2)
                                     : make_float2(1e5f, 1e5f);
            *(float2*)(sm + AKPOS + st * 512 + tid * 8) = v;
        }
    };

    load_tile(0, 0);
    load_tile(1, 1);

    float m_0 = -1e30f, m_1 = -1e30f, l_0 = 0.f, l_1 = 0.f;
    float oacc[18][4];
    #pragma unroll
    for (int a = 0; a < 18; a++)
        #pragma unroll
        for (int q = 0; q < 4; q++) oacc[a][q] = 0.f;

    const int NT = (HW_DIM + 63) / 64;   // 12
    for (int kt = 0; kt < NT; kt++) {
        const int st = kt % ANST;
        if (kt < NT - 1) asm volatile("cp.async.wait_group 1;" ::: "memory");
        else             asm volatile("cp.async.wait_group 0;" ::: "memory");
        __syncthreads();

        if (kt + 2 < NT) load_tile((kt + 2) % ANST, kt + 2);

        uint32_t stb = sb + (uint32_t)st * (uint32_t)ASTG;
        uint32_t lrow = (uint32_t)(lane & 15) * APITCH + (uint32_t)(lane >> 4) * 16u;
        uint32_t khb = stb + lrow;
        uint32_t vhb = stb + ATSZ + lrow;

        float sacc[8][4];
        #pragma unroll
        for (int a = 0; a < 8; a++)
            #pragma unroll
            for (int q = 0; q < 4; q++) sacc[a][q] = 0.f;

        uint32_t bhf[2][4][4];
        #pragma unroll
        for (int g = 0; g < 4; g++) ldm4(khb + g * (16 * APITCH), bhf[0][g]);
        #pragma unroll
        for (int kc = 0; kc < 9; kc++) {
            const int cur = kc & 1, nxt = cur ^ 1;
            if (kc < 8) {
                #pragma unroll
                for (int g = 0; g < 4; g++)
                    ldm4(khb + g * (16 * APITCH) + (kc + 1) * 32, bhf[nxt][g]);
            }
            #pragma unroll
            for (int g = 0; g < 4; g++) {
                mma_f16(sacc[2*g],   qf[kc], bhf[cur][g][0], bhf[cur][g][2]);
                mma_f16(sacc[2*g+1], qf[kc], bhf[cur][g][1], bhf[cur][g][3]);
            }
        }

        const float2* kp = (const float2*)(sm + AKPOS + st * 512);
        float mn0 = m_0, mn1 = m_1;
        #pragma unroll
        for (int a = 0; a < 8; a++) {
            int c0 = a * 8 + tig * 2;
            float2 ka = kp[c0];
            float2 kb = kp[c0 + 1];
            float dxa0 = qp0.x - ka.x, dya0 = qp0.y - ka.y;
            float dxb0 = qp0.x - kb.x, dyb0 = qp0.y - kb.y;
            float dxa1 = qp1.x - ka.x, dya1 = qp1.y - ka.y;
            float dxb1 = qp1.x - kb.x, dyb1 = qp1.y - kb.y;
            sacc[a][0] = sacc[a][0] * SC_QK - (dxa0*dxa0 + dya0*dya0) * SC_BIAS;
            sacc[a][1] = sacc[a][1] * SC_QK - (dxb0*dxb0 + dyb0*dyb0) * SC_BIAS;
            sacc[a][2] = sacc[a][2] * SC_QK - (dxa1*dxa1 + dya1*dya1) * SC_BIAS;
            sacc[a][3] = sacc[a][3] * SC_QK - (dxb1*dxb1 + dyb1*dyb1) * SC_BIAS;
            mn0 = fmaxf(mn0, fmaxf(sacc[a][0], sacc[a][1]));
            mn1 = fmaxf(mn1, fmaxf(sacc[a][2], sacc[a][3]));
        }
        mn0 = fmaxf(mn0, __shfl_xor_sync(0xffffffffu, mn0, 1));
        mn0 = fmaxf(mn0, __shfl_xor_sync(0xffffffffu, mn0, 2));
        mn1 = fmaxf(mn1, __shfl_xor_sync(0xffffffffu, mn1, 1));
        mn1 = fmaxf(mn1, __shfl_xor_sync(0xffffffffu, mn1, 2));

        bool changed = (mn0 > m_0) || (mn1 > m_1);
        if (__any_sync(0xffffffffu, changed)) {
            float corr0 = exp2f(m_0 - mn0);
            float corr1 = exp2f(m_1 - mn1);
            m_0 = mn0; m_1 = mn1;
            l_0 *= corr0; l_1 *= corr1;
            #pragma unroll
            for (int a = 0; a < 18; a++) {
                oacc[a][0] *= corr0; oacc[a][1] *= corr0;
                oacc[a][2] *= corr1; oacc[a][3] *= corr1;
            }
        }

        #pragma unroll
        for (int a = 0; a < 8; a++) {
            float p0 = exp2f(sacc[a][0] - m_0);
            float p1 = exp2f(sacc[a][1] - m_0);
            float p2 = exp2f(sacc[a][2] - m_1);
            float p3 = exp2f(sacc[a][3] - m_1);
            l_0 += p0 + p1; l_1 += p2 + p3;
            sacc[a][0] = p0; sacc[a][1] = p1; sacc[a][2] = p2; sacc[a][3] = p3;
        }

        #pragma unroll
        for (int kc4 = 0; kc4 < 4; kc4++) {
            uint32_t pa[4];
            pa[0] = pack_h2(sacc[2*kc4][0],   sacc[2*kc4][1]);
            pa[1] = pack_h2(sacc[2*kc4][2],   sacc[2*kc4][3]);
            pa[2] = pack_h2(sacc[2*kc4+1][0], sacc[2*kc4+1][1]);
            pa[3] = pack_h2(sacc[2*kc4+1][2], sacc[2*kc4+1][3]);
            uint32_t vf[2][4];
            ldm4t(vhb + kc4 * (16 * APITCH), vf[0]);
            #pragma unroll
            for (int dp = 0; dp < 9; dp++) {
                const int cur = dp & 1, nxt = cur ^ 1;
                if (dp < 8)
                    ldm4t(vhb + kc4 * (16 * APITCH) + (dp + 1) * 32, vf[nxt]);
                mma_f16(oacc[2*dp],   pa, vf[cur][0], vf[cur][1]);
                mma_f16(oacc[2*dp+1], pa, vf[cur][2], vf[cur][3]);
            }
        }
    }

    l_0 += __shfl_xor_sync(0xffffffffu, l_0, 1);
    l_0 += __shfl_xor_sync(0xffffffffu, l_0, 2);
    l_1 += __shfl_xor_sync(0xffffffffu, l_1, 1);
    l_1 += __shfl_xor_sync(0xffffffffu, l_1, 2);
    float inv0 = 1.f / l_0, inv1 = 1.f / l_1;

    size_t row0 = (size_t)t * M_TRK + m0 + w * 16 + gid;
    #pragma unroll
    for (int a = 0; a < 18; a++) {
        int col = h * DH + a * 8 + tig * 2;
        *(__half2*)(Sh + row0 * DM + col) =
            __floats2half2_rn(oacc[a][0] * inv0, oacc[a][1] * inv0);
        *(__half2*)(Sh + (row0 + 8) * DM + col) =
            __floats2half2_rn(oacc[a][2] * inv1, oacc[a][3] * inv1);
    }
}

// ---------------- launch (dual-stream fork/join) ----------------
extern "C" void kernel_launch(void* const* d_in, const int* in_sizes, int n_in,
                              void* d_out, int out_size)
{
    const float* features    = (const float*)d_in[0];
    const float* tracks      = (const float*)d_in[1];
    const float* track_toks  = (const float*)d_in[2];
    const float* fpos        = (const float*)d_in[3];
    const float* W_q         = (const float*)d_in[4];
    const float* W_k         = (const float*)d_in[5];
    const float* q_norm_w    = (const float*)d_in[6];
    const float* k_norm_w    = (const float*)d_in[7];
    const float* out_proj_w  = (const float*)d_in[8];
    float* out = (float*)d_out;

    __half *gQg, *gKg, *gTTh, *gFh, *gWq, *gWk, *gWo, *gQh, *gKh, *gSh;
    cudaGetSymbolAddress((void**)&gQg, g_Qg);
    cudaGetSymbolAddress((void**)&gKg, g_Kg);
    cudaGetSymbolAddress((void**)&gTTh, g_TTh);
    cudaGetSymbolAddress((void**)&gFh, g_Fh);
    cudaGetSymbolAddress((void**)&gWq, g_Wq);
    cudaGetSymbolAddress((void**)&gWk, g_Wk);
    cudaGetSymbolAddress((void**)&gWo, g_Wo);
    cudaGetSymbolAddress((void**)&gQh, g_Qh);
    cudaGetSymbolAddress((void**)&gKh, g_Kh);
    cudaGetSymbolAddress((void**)&gSh, g_Sh);

    cudaFuncSetAttribute(gemm_h_kernel,
                         cudaFuncAttributeMaxDynamicSharedMemorySize, GEMM_SMEM);
    cudaFuncSetAttribute(gemm_out_kernel,
                         cudaFuncAttributeMaxDynamicSharedMemorySize, GEMM_SMEM);
    cudaFuncSetAttribute(attn_mma_kernel,
                         cudaFuncAttributeMaxDynamicSharedMemorySize, ATTN_SMEM);

    cudaStream_t sA, sB;
    cudaStreamCreateWithFlags(&sA, cudaStreamNonBlocking);
    cudaStreamCreateWithFlags(&sB, cudaStreamNonBlocking);
    cudaEvent_t evPrep, evA, evB;
    cudaEventCreateWithFlags(&evPrep, cudaEventDisableTiming);
    cudaEventCreateWithFlags(&evA, cudaEventDisableTiming);
    cudaEventCreateWithFlags(&evB, cudaEventDisableTiming);

    // ---- single merged preprocessing launch (origin stream) ----
    prep_kernel<<<PREP_TOT, 256>>>(track_toks, gTTh, features, gFh,
                                   W_q, gWq, W_k, gWk, out_proj_w, gWo, fpos);
    cudaEventRecord(evPrep, 0);
    cudaStreamWaitEvent(sA, evPrep, 0);
    cudaStreamWaitEvent(sB, evPrep, 0);

    // ---- stream A: K = features @ W_k, then RoPE+LN(K) ----
    {
        dim3 g(DM / 128, MKB);
        gemm_h_kernel<<<g, 128, GEMM_SMEM, sA>>>(gFh, gWk, gKg, MK);
    }
    ln_k_kernel<<<MK, 192, 0, sA>>>(gKg, k_norm_w, gKh);
    cudaEventRecord(evA, sA);

    // ---- stream B: Q = track_tokens @ W_q, then LN(Q) ----
    {
        dim3 g(DM / 128, MQB);
        gemm_h_kernel<<<g, 128, GEMM_SMEM, sB>>>(gTTh, gWq, gQg, MQ);
    }
    ln_q_kernel<<<MQ, 192, 0, sB>>>(gQg, q_norm_w, gQh);
    cudaEventRecord(evB, sB);

    // ---- join back onto origin stream ----
    cudaStreamWaitEvent(0, evA, 0);
    cudaStreamWaitEvent(0, evB, 0);

    // ---- fused tensor-core attention (V = features fp16) ----
    {
        dim3 g(M_TRK / 128, NH, T_DIM);
        attn_mma_kernel<<<g, 256, ATTN_SMEM>>>(gQh, gKh, gFh, tracks, fpos, gSh);
    }

    // ---- out = sampled @ out_proj_w (fp32 out) ----
    {
        dim3 g(DM / 128, MQB);
        gemm_out_kernel<<<g, 128, GEMM_SMEM>>>(gSh, gWo, out, MQ);
    }

    cudaEventDestroy(evPrep);
    cudaEventDestroy(evA);
    cudaEventDestroy(evB);
    cudaStreamDestroy(sA);
    cudaStreamDestroy(sB);
}